// round 4
// baseline (speedup 1.0000x reference)
#include <cuda_runtime.h>
#include <cuda_bf16.h>
#include <math.h>

#define NBATCH 16
#define CI 32
#define CO 64
#define HH 128
#define WW 128
#define DS 5
#define KK 800     // CI*DS*DS
#define BS 100     // Cholesky panel
#define NSTEP 8    // KK/BS

// ---------------- scratch (static device allocations are allowed) ----------
__device__ float g_R[NBATCH][CI][CI][9][9];   // channel autocorrelation
__device__ float g_Q[NBATCH][KK][KK];         // Gram matrix -> Cholesky factor (lower)
__device__ float g_P[NBATCH][KK][CO];         // RHS -> z -> solution

// ===========================================================================
// Kernel 1: R[n,a,b,du,dv] = sum_ij x[n,a,i,j]*x[n,b,i+du-4,j+dv-4]
// one block per (pair a<=b, batch). 256 thr = 16 rows x 16 col-chunks(8).
// ===========================================================================
__global__ __launch_bounds__(256) void gram_kernel(const float* __restrict__ x)
{
    int n = blockIdx.y;
    int p = blockIdx.x;
    int a = 0, rem = p;
    while (rem >= CI - a) { rem -= CI - a; a++; }
    int b = a + rem;

    const float* __restrict__ xa = x + ((size_t)n * CI + a) * (HH * WW);
    const float* __restrict__ xb = x + ((size_t)n * CI + b) * (HH * WW);

    __shared__ float sxa[16][128];
    __shared__ float sxb[24][136];
    __shared__ float sred[8][81];

    int tid  = threadIdx.x;
    int ty   = tid >> 4;
    int tx   = tid & 15;
    int lane = tid & 31;
    int wid  = tid >> 5;

    float acc[81];
#pragma unroll
    for (int q = 0; q < 81; q++) acc[q] = 0.f;

    for (int s = 0; s < 8; s++) {
        int r0 = s * 16;
        // load xa stripe (rows r0..r0+16)
        {
            const float4* src = (const float4*)(xa + (size_t)(r0 + ty) * WW);
            float4* dst = (float4*)(&sxa[ty][0]);
            dst[tx * 2]     = src[tx * 2];
            dst[tx * 2 + 1] = src[tx * 2 + 1];
        }
        // load xb stripe with halo 4 (rows r0-4..r0+20, cols -4..132)
        for (int idx = tid; idx < 24 * 136; idx += 256) {
            int rr = idx / 136, cc = idx - rr * 136;
            int gr = r0 + rr - 4, gc = cc - 4;
            float v = 0.f;
            if (gr >= 0 && gr < HH && gc >= 0 && gc < WW)
                v = xb[(size_t)gr * WW + gc];
            sxb[rr][cc] = v;
        }
        __syncthreads();

        float xav[8];
#pragma unroll
        for (int t = 0; t < 8; t++) xav[t] = sxa[ty][tx * 8 + t];

#pragma unroll
        for (int du = 0; du < 9; du++) {
            float xbv[16];
            const float4* row = (const float4*)(&sxb[ty + du][tx * 8]);
#pragma unroll
            for (int q4 = 0; q4 < 4; q4++) {
                float4 v = row[q4];
                xbv[q4 * 4 + 0] = v.x; xbv[q4 * 4 + 1] = v.y;
                xbv[q4 * 4 + 2] = v.z; xbv[q4 * 4 + 3] = v.w;
            }
#pragma unroll
            for (int t = 0; t < 8; t++)
#pragma unroll
                for (int dv = 0; dv < 9; dv++)
                    acc[du * 9 + dv] += xav[t] * xbv[t + dv];
        }
        __syncthreads();
    }

    // reduce 81 accumulators across block
#pragma unroll
    for (int q = 0; q < 81; q++) {
        float v = acc[q];
        for (int o = 16; o; o >>= 1) v += __shfl_down_sync(0xffffffffu, v, o);
        if (lane == 0) sred[wid][q] = v;
    }
    __syncthreads();
    if (tid < 81) {
        float v = 0.f;
#pragma unroll
        for (int w = 0; w < 8; w++) v += sred[w][tid];
        int u = tid / 9, vv = tid - u * 9;
        g_R[n][a][b][u][vv] = v;
        g_R[n][b][a][8 - u][8 - vv] = v;   // symmetry (for a==b same value)
    }
}

// ===========================================================================
// Kernel 2: S -> P[n,(b,u,v),o] = sum_ij y[n,o,i,j]*x[n,b,i+u-2,j+v-2]
// one block per (o,b,batch)
// ===========================================================================
__global__ __launch_bounds__(256) void scorr_kernel(const float* __restrict__ x,
                                                    const float* __restrict__ y)
{
    int n = blockIdx.y;
    int o = blockIdx.x >> 5;
    int b = blockIdx.x & 31;

    const float* __restrict__ ya = y + ((size_t)n * CO + o) * (HH * WW);
    const float* __restrict__ xb = x + ((size_t)n * CI + b) * (HH * WW);

    __shared__ float sya[16][128];
    __shared__ float sxb[20][132];
    __shared__ float sred[8][25];

    int tid  = threadIdx.x;
    int ty   = tid >> 4;
    int tx   = tid & 15;
    int lane = tid & 31;
    int wid  = tid >> 5;

    float acc[25];
#pragma unroll
    for (int q = 0; q < 25; q++) acc[q] = 0.f;

    for (int s = 0; s < 8; s++) {
        int r0 = s * 16;
        {
            const float4* src = (const float4*)(ya + (size_t)(r0 + ty) * WW);
            float4* dst = (float4*)(&sya[ty][0]);
            dst[tx * 2]     = src[tx * 2];
            dst[tx * 2 + 1] = src[tx * 2 + 1];
        }
        for (int idx = tid; idx < 20 * 132; idx += 256) {
            int rr = idx / 132, cc = idx - rr * 132;
            int gr = r0 + rr - 2, gc = cc - 2;
            float v = 0.f;
            if (gr >= 0 && gr < HH && gc >= 0 && gc < WW)
                v = xb[(size_t)gr * WW + gc];
            sxb[rr][cc] = v;
        }
        __syncthreads();

        float yav[8];
#pragma unroll
        for (int t = 0; t < 8; t++) yav[t] = sya[ty][tx * 8 + t];

#pragma unroll
        for (int du = 0; du < 5; du++) {
            float xbv[12];
            const float4* row = (const float4*)(&sxb[ty + du][tx * 8]);
#pragma unroll
            for (int q4 = 0; q4 < 3; q4++) {
                float4 v = row[q4];
                xbv[q4 * 4 + 0] = v.x; xbv[q4 * 4 + 1] = v.y;
                xbv[q4 * 4 + 2] = v.z; xbv[q4 * 4 + 3] = v.w;
            }
#pragma unroll
            for (int t = 0; t < 8; t++)
#pragma unroll
                for (int dv = 0; dv < 5; dv++)
                    acc[du * 5 + dv] += yav[t] * xbv[t + dv];
        }
        __syncthreads();
    }

#pragma unroll
    for (int q = 0; q < 25; q++) {
        float v = acc[q];
        for (int oo = 16; oo; oo >>= 1) v += __shfl_down_sync(0xffffffffu, v, oo);
        if (lane == 0) sred[wid][q] = v;
    }
    __syncthreads();
    if (tid < 25) {
        float v = 0.f;
#pragma unroll
        for (int w = 0; w < 8; w++) v += sred[w][tid];
        int u = tid / 5, vv = tid - u * 5;
        int k = b * 25 + u * 5 + vv;
        g_P[n][k][o] = v;
    }
}

// ===========================================================================
// Kernel 3: expand Q from R, add ridge on diagonal
// ===========================================================================
__global__ void assembleQ_kernel(const float* __restrict__ alpha,
                                 const float* __restrict__ regp)
{
    int n  = blockIdx.y;
    int k1 = blockIdx.x;
    int a = k1 / 25, r = (k1 / 5) % 5, s = k1 % 5;
    float an = alpha[n] * ((float)(HH * WW) * regp[0] / (float)(DS * DS * CI));
    for (int k2 = threadIdx.x; k2 < KK; k2 += 256) {
        int bb = k2 / 25, pp = (k2 / 5) % 5, tt = k2 % 5;
        float v = g_R[n][a][bb][pp - r + 4][tt - s + 4];
        if (k2 == k1) v += an;
        g_Q[n][k1][k2] = v;
    }
}

// Kernel 4: P += a_n * d^T
__global__ void assembleP_kernel(const float* __restrict__ d,
                                 const float* __restrict__ alpha,
                                 const float* __restrict__ regp)
{
    int n = blockIdx.y;
    int k = blockIdx.x;
    int o = threadIdx.x;
    float an = alpha[n] * ((float)(HH * WW) * regp[0] / (float)(DS * DS * CI));
    g_P[n][k][o] += an * d[((size_t)n * CO + o) * KK + k];
}

// ===========================================================================
// Cholesky: panel potrf (in shared), one block per batch
// ===========================================================================
__global__ __launch_bounds__(256) void potrf_kernel(int k0)
{
    int n = blockIdx.x;
    __shared__ float A[BS][BS + 1];
    __shared__ float sinv;
    int tid = threadIdx.x;
    int lane = tid & 31, wid = tid >> 5;

    for (int idx = tid; idx < BS * BS; idx += 256) {
        int i = idx / BS, j = idx - i * BS;
        A[i][j] = g_Q[n][k0 + i][k0 + j];
    }
    __syncthreads();

    for (int j = 0; j < BS; j++) {
        if (tid == 0) {
            float s = sqrtf(A[j][j]);
            A[j][j] = s;
            sinv = 1.0f / s;
        }
        __syncthreads();
        float inv = sinv;
        for (int i = j + 1 + tid; i < BS; i += 256) A[i][j] *= inv;
        __syncthreads();
        for (int i = j + 1 + wid; i < BS; i += 8) {
            float aij = A[i][j];
            for (int k = j + 1 + lane; k <= i; k += 32)
                A[i][k] -= aij * A[k][j];
        }
        __syncthreads();
    }

    for (int idx = tid; idx < BS * BS; idx += 256) {
        int i = idx / BS, j = idx - i * BS;
        if (j <= i) g_Q[n][k0 + i][k0 + j] = A[i][j];
    }
}

// trsm: A21 <- A21 * L11^{-T}   (warp-per-row forward substitution)
__global__ __launch_bounds__(256) void trsm_kernel(int k0)
{
    int n = blockIdx.y;
    int rowbase = k0 + BS + blockIdx.x * 8;
    __shared__ float L[BS][BS + 1];
    __shared__ float inv[BS];
    int tid = threadIdx.x;
    int lane = tid & 31, wid = tid >> 5;

    for (int idx = tid; idx < BS * BS; idx += 256) {
        int i = idx / BS, j = idx - i * BS;
        L[i][j] = (j <= i) ? g_Q[n][k0 + i][k0 + j] : 0.f;
    }
    __syncthreads();
    if (tid < BS) inv[tid] = 1.0f / L[tid][tid];
    __syncthreads();

    int r = rowbase + wid;
    if (r < KK) {
        float v[4];
#pragma unroll
        for (int q = 0; q < 4; q++) {
            int m = lane + 32 * q;
            v[q] = (m < BS) ? g_Q[n][r][k0 + m] : 0.f;
        }
        for (int j = 0; j < BS; j++) {
            int srcq = j >> 5, srclane = j & 31;
            float vj = (srcq == 0) ? v[0] : (srcq == 1) ? v[1] : (srcq == 2) ? v[2] : v[3];
            vj = __shfl_sync(0xffffffffu, vj, srclane);
            vj *= inv[j];
            if (lane == srclane) {
                if (srcq == 0) v[0] = vj; else if (srcq == 1) v[1] = vj;
                else if (srcq == 2) v[2] = vj; else v[3] = vj;
            }
#pragma unroll
            for (int q = 0; q < 4; q++) {
                int m = lane + 32 * q;
                if (m > j && m < BS) v[q] -= L[m][j] * vj;
            }
        }
#pragma unroll
        for (int q = 0; q < 4; q++) {
            int m = lane + 32 * q;
            if (m < BS) g_Q[n][r][k0 + m] = v[q];
        }
    }
}

// syrk: A22 -= L21 * L21^T  (lower tiles only), 64x64 tiles, K=100
__global__ __launch_bounds__(256) void syrk_kernel(int k0)
{
    int off = k0 + BS;
    int m = KK - off;
    int nt = (m + 63) >> 6;
    int n = blockIdx.y;
    int p = blockIdx.x;
    int tj = 0;
    while (p >= nt - tj) { p -= nt - tj; tj++; }
    int ti = tj + p;

    __shared__ float LA[64][21];
    __shared__ float LB[64][21];
    int tid = threadIdx.x;
    int txx = tid & 15, tyy = tid >> 4;

    float c[4][4];
#pragma unroll
    for (int i = 0; i < 4; i++)
#pragma unroll
        for (int j = 0; j < 4; j++) c[i][j] = 0.f;

    int rbase = off + ti * 64, cbase = off + tj * 64;
    for (int kk = 0; kk < BS; kk += 20) {
        for (int idx = tid; idx < 64 * 20; idx += 256) {
            int rr = idx / 20, k = idx - rr * 20;
            LA[rr][k] = (rbase + rr < KK) ? g_Q[n][rbase + rr][k0 + kk + k] : 0.f;
        }
        for (int idx = tid; idx < 64 * 20; idx += 256) {
            int rr = idx / 20, k = idx - rr * 20;
            LB[rr][k] = (cbase + rr < KK) ? g_Q[n][cbase + rr][k0 + kk + k] : 0.f;
        }
        __syncthreads();
#pragma unroll
        for (int k = 0; k < 20; k++) {
            float ra[4], rb[4];
#pragma unroll
            for (int i = 0; i < 4; i++) ra[i] = LA[tyy * 4 + i][k];
#pragma unroll
            for (int j = 0; j < 4; j++) rb[j] = LB[txx * 4 + j][k];
#pragma unroll
            for (int i = 0; i < 4; i++)
#pragma unroll
                for (int j = 0; j < 4; j++) c[i][j] += ra[i] * rb[j];
        }
        __syncthreads();
    }
#pragma unroll
    for (int i = 0; i < 4; i++) {
        int gr = rbase + tyy * 4 + i;
        if (gr < KK) {
#pragma unroll
            for (int j = 0; j < 4; j++) {
                int gc = cbase + txx * 4 + j;
                if (gc < KK) g_Q[n][gr][gc] -= c[i][j];
            }
        }
    }
}

// ===========================================================================
// triangular solves with 64 RHS
// forward diag: solve L_ii * Z_i = P_i  (warp per column, right-looking)
// ===========================================================================
__global__ __launch_bounds__(1024) void trsv_fwd_kernel(int k0)
{
    int n = blockIdx.x;
    int chalf = blockIdx.y;
    __shared__ float L[BS][BS + 1];
    __shared__ float inv[BS];
    int tid = threadIdx.x;
    int lane = tid & 31, w = tid >> 5;

    for (int idx = tid; idx < BS * BS; idx += 1024) {
        int i = idx / BS, j = idx - i * BS;
        L[i][j] = (j <= i) ? g_Q[n][k0 + i][k0 + j] : 0.f;
    }
    __syncthreads();
    if (tid < BS) inv[tid] = 1.0f / L[tid][tid];
    __syncthreads();

    int c = chalf * 32 + w;
    float v[4];
#pragma unroll
    for (int q = 0; q < 4; q++) {
        int m = lane + 32 * q;
        v[q] = (m < BS) ? g_P[n][k0 + m][c] : 0.f;
    }
    for (int j = 0; j < BS; j++) {
        int srcq = j >> 5, srclane = j & 31;
        float vj = (srcq == 0) ? v[0] : (srcq == 1) ? v[1] : (srcq == 2) ? v[2] : v[3];
        vj = __shfl_sync(0xffffffffu, vj, srclane);
        vj *= inv[j];
        if (lane == srclane) {
            if (srcq == 0) v[0] = vj; else if (srcq == 1) v[1] = vj;
            else if (srcq == 2) v[2] = vj; else v[3] = vj;
        }
#pragma unroll
        for (int q = 0; q < 4; q++) {
            int m = lane + 32 * q;
            if (m > j && m < BS) v[q] -= L[m][j] * vj;
        }
    }
#pragma unroll
    for (int q = 0; q < 4; q++) {
        int m = lane + 32 * q;
        if (m < BS) g_P[n][k0 + m][c] = v[q];
    }
}

// backward diag: solve L_ii^T * D_i = Z_i
__global__ __launch_bounds__(1024) void trsv_bwd_kernel(int k0)
{
    int n = blockIdx.x;
    int chalf = blockIdx.y;
    __shared__ float L[BS][BS + 1];
    __shared__ float inv[BS];
    int tid = threadIdx.x;
    int lane = tid & 31, w = tid >> 5;

    for (int idx = tid; idx < BS * BS; idx += 1024) {
        int i = idx / BS, j = idx - i * BS;
        L[i][j] = (j <= i) ? g_Q[n][k0 + i][k0 + j] : 0.f;
    }
    __syncthreads();
    if (tid < BS) inv[tid] = 1.0f / L[tid][tid];
    __syncthreads();

    int c = chalf * 32 + w;
    float v[4];
#pragma unroll
    for (int q = 0; q < 4; q++) {
        int m = lane + 32 * q;
        v[q] = (m < BS) ? g_P[n][k0 + m][c] : 0.f;
    }
    for (int j = BS - 1; j >= 0; j--) {
        int srcq = j >> 5, srclane = j & 31;
        float vj = (srcq == 0) ? v[0] : (srcq == 1) ? v[1] : (srcq == 2) ? v[2] : v[3];
        vj = __shfl_sync(0xffffffffu, vj, srclane);
        vj *= inv[j];
        if (lane == srclane) {
            if (srcq == 0) v[0] = vj; else if (srcq == 1) v[1] = vj;
            else if (srcq == 2) v[2] = vj; else v[3] = vj;
        }
#pragma unroll
        for (int q = 0; q < 4; q++) {
            int m = lane + 32 * q;
            if (m < j) v[q] -= L[j][m] * vj;
        }
    }
#pragma unroll
    for (int q = 0; q < 4; q++) {
        int m = lane + 32 * q;
        if (m < BS) g_P[n][k0 + m][c] = v[q];
    }
}

// forward update: P[off.. , :] -= L[off.. , k0:k0+100] * Z[k0:k0+100, :]
__global__ __launch_bounds__(256) void fsolve_update_kernel(int k0)
{
    int off = k0 + BS;
    int n = blockIdx.y;
    int rbase = off + blockIdx.x * 64;

    __shared__ float LA[64][21];
    __shared__ float BB[20][65];
    int tid = threadIdx.x;
    int txx = tid & 15, tyy = tid >> 4;

    float c[4][4];
#pragma unroll
    for (int i = 0; i < 4; i++)
#pragma unroll
        for (int j = 0; j < 4; j++) c[i][j] = 0.f;

    for (int kk = 0; kk < BS; kk += 20) {
        for (int idx = tid; idx < 64 * 20; idx += 256) {
            int rr = idx / 20, k = idx - rr * 20;
            LA[rr][k] = (rbase + rr < KK) ? g_Q[n][rbase + rr][k0 + kk + k] : 0.f;
        }
        for (int idx = tid; idx < 20 * 64; idx += 256) {
            int k = idx >> 6, cc = idx & 63;
            BB[k][cc] = g_P[n][k0 + kk + k][cc];
        }
        __syncthreads();
#pragma unroll
        for (int k = 0; k < 20; k++) {
            float ra[4], rb[4];
#pragma unroll
            for (int i = 0; i < 4; i++) ra[i] = LA[tyy * 4 + i][k];
#pragma unroll
            for (int j = 0; j < 4; j++) rb[j] = BB[k][txx * 4 + j];
#pragma unroll
            for (int i = 0; i < 4; i++)
#pragma unroll
                for (int j = 0; j < 4; j++) c[i][j] += ra[i] * rb[j];
        }
        __syncthreads();
    }
#pragma unroll
    for (int i = 0; i < 4; i++) {
        int gr = rbase + tyy * 4 + i;
        if (gr < KK) {
#pragma unroll
            for (int j = 0; j < 4; j++)
                g_P[n][gr][txx * 4 + j] -= c[i][j];
        }
    }
}

// backward update: Z[0:k0, :] -= L[k0:k0+100, 0:k0]^T * D[k0:k0+100, :]
__global__ __launch_bounds__(256) void bsolve_update_kernel(int k0)
{
    int n = blockIdx.y;
    int rbase = blockIdx.x * 64;

    __shared__ float AT[20][65];
    __shared__ float BB[20][65];
    int tid = threadIdx.x;
    int txx = tid & 15, tyy = tid >> 4;

    float c[4][4];
#pragma unroll
    for (int i = 0; i < 4; i++)
#pragma unroll
        for (int j = 0; j < 4; j++) c[i][j] = 0.f;

    for (int kk = 0; kk < BS; kk += 20) {
        for (int idx = tid; idx < 20 * 64; idx += 256) {
            int k = idx >> 6, rl = idx & 63;
            AT[k][rl] = g_Q[n][k0 + kk + k][rbase + rl];
        }
        for (int idx = tid; idx < 20 * 64; idx += 256) {
            int k = idx >> 6, cc = idx & 63;
            BB[k][cc] = g_P[n][k0 + kk + k][cc];
        }
        __syncthreads();
#pragma unroll
        for (int k = 0; k < 20; k++) {
            float ra[4], rb[4];
#pragma unroll
            for (int i = 0; i < 4; i++) ra[i] = AT[k][tyy * 4 + i];
#pragma unroll
            for (int j = 0; j < 4; j++) rb[j] = BB[k][txx * 4 + j];
#pragma unroll
            for (int i = 0; i < 4; i++)
#pragma unroll
                for (int j = 0; j < 4; j++) c[i][j] += ra[i] * rb[j];
        }
        __syncthreads();
    }
#pragma unroll
    for (int i = 0; i < 4; i++) {
        int gr = rbase + tyy * 4 + i;
        if (gr < k0) {
#pragma unroll
            for (int j = 0; j < 4; j++)
                g_P[n][gr][txx * 4 + j] -= c[i][j];
        }
    }
}

// final transpose: out[n][o][k] = P[n][k][o]
__global__ void output_kernel(float* __restrict__ out)
{
    int n = blockIdx.y;
    int k = blockIdx.x;
    int o = threadIdx.x;
    out[((size_t)n * CO + o) * KK + k] = g_P[n][k][o];
}

// ===========================================================================
extern "C" void kernel_launch(void* const* d_in, const int* in_sizes, int n_in,
                              void* d_out, int out_size)
{
    const float* x     = (const float*)d_in[0];   // (16,1,32,128,128)
    const float* d     = (const float*)d_in[1];   // (16,64,32,5,5)
    const float* y     = (const float*)d_in[2];   // (16,64,1,128,128)
    const float* alpha = (const float*)d_in[3];   // (16,1,1,1)
    const float* regp  = (const float*)d_in[4];   // scalar

    gram_kernel <<<dim3(528,  NBATCH), 256>>>(x);
    scorr_kernel<<<dim3(2048, NBATCH), 256>>>(x, y);
    assembleQ_kernel<<<dim3(KK, NBATCH), 256>>>(alpha, regp);
    assembleP_kernel<<<dim3(KK, NBATCH), 64>>>(d, alpha, regp);

    // blocked Cholesky
    for (int s = 0; s < NSTEP; s++) {
        int k0 = s * BS;
        potrf_kernel<<<NBATCH, 256>>>(k0);
        int rows = KK - k0 - BS;
        if (rows > 0) {
            trsm_kernel<<<dim3((rows + 7) / 8, NBATCH), 256>>>(k0);
            int nt = (rows + 63) / 64;
            syrk_kernel<<<dim3(nt * (nt + 1) / 2, NBATCH), 256>>>(k0);
        }
    }
    // forward substitution
    for (int s = 0; s < NSTEP; s++) {
        int k0 = s * BS;
        trsv_fwd_kernel<<<dim3(NBATCH, 2), 1024>>>(k0);
        int rows = KK - k0 - BS;
        if (rows > 0)
            fsolve_update_kernel<<<dim3((rows + 63) / 64, NBATCH), 256>>>(k0);
    }
    // backward substitution
    for (int s = NSTEP - 1; s >= 0; s--) {
        int k0 = s * BS;
        trsv_bwd_kernel<<<dim3(NBATCH, 2), 1024>>>(k0);
        if (k0 > 0)
            bsolve_update_kernel<<<dim3((k0 + 63) / 64, NBATCH), 256>>>(k0);
    }

    output_kernel<<<dim3(KK, NBATCH), 64>>>((float*)d_out);
}

// round 6
// speedup vs baseline: 1.1061x; 1.1061x over previous
#include <cuda_runtime.h>
#include <cuda_bf16.h>
#include <math.h>

#define NBATCH 16
#define CI 32
#define CO 64
#define HH 128
#define WW 128
#define DS 5
#define KK 800     // CI*DS*DS
#define BS 100     // Cholesky panel
#define NSTEP 8    // KK/BS

// ---------------- scratch ----------
__device__ float g_R[NBATCH][CI][CI][9][9];   // channel autocorrelation
__device__ float g_Q[NBATCH][KK][KK];         // Gram matrix -> Cholesky factor (lower)
__device__ float g_P[NBATCH][KK][CO];         // RHS -> z -> solution

// ===========================================================================
// Kernel 1: R[n,a,b,du,dv] = sum_ij x[n,a,i,j]*x[n,b,i+du-4,j+dv-4]
// one block per (pair a<=b, batch). 256 thr = 16 rows x 16 col-chunks(8).
// ===========================================================================
__global__ __launch_bounds__(256) void gram_kernel(const float* __restrict__ x)
{
    int n = blockIdx.y;
    int p = blockIdx.x;
    int a = 0, rem = p;
    while (rem >= CI - a) { rem -= CI - a; a++; }
    int b = a + rem;

    const float* __restrict__ xa = x + ((size_t)n * CI + a) * (HH * WW);
    const float* __restrict__ xb = x + ((size_t)n * CI + b) * (HH * WW);

    __shared__ float sxa[16][128];
    __shared__ float sxb[24][136];
    __shared__ float sred[8][81];

    int tid  = threadIdx.x;
    int ty   = tid >> 4;
    int tx   = tid & 15;
    int lane = tid & 31;
    int wid  = tid >> 5;

    float acc[81];
#pragma unroll
    for (int q = 0; q < 81; q++) acc[q] = 0.f;

    for (int s = 0; s < 8; s++) {
        int r0 = s * 16;
        {
            const float4* src = (const float4*)(xa + (size_t)(r0 + ty) * WW);
            float4* dst = (float4*)(&sxa[ty][0]);
            dst[tx * 2]     = src[tx * 2];
            dst[tx * 2 + 1] = src[tx * 2 + 1];
        }
        for (int idx = tid; idx < 24 * 136; idx += 256) {
            int rr = idx / 136, cc = idx - rr * 136;
            int gr = r0 + rr - 4, gc = cc - 4;
            float v = 0.f;
            if (gr >= 0 && gr < HH && gc >= 0 && gc < WW)
                v = xb[(size_t)gr * WW + gc];
            sxb[rr][cc] = v;
        }
        __syncthreads();

        float xav[8];
#pragma unroll
        for (int t = 0; t < 8; t++) xav[t] = sxa[ty][tx * 8 + t];

#pragma unroll
        for (int du = 0; du < 9; du++) {
            float xbv[16];
            const float4* row = (const float4*)(&sxb[ty + du][tx * 8]);
#pragma unroll
            for (int q4 = 0; q4 < 4; q4++) {
                float4 v = row[q4];
                xbv[q4 * 4 + 0] = v.x; xbv[q4 * 4 + 1] = v.y;
                xbv[q4 * 4 + 2] = v.z; xbv[q4 * 4 + 3] = v.w;
            }
#pragma unroll
            for (int t = 0; t < 8; t++)
#pragma unroll
                for (int dv = 0; dv < 9; dv++)
                    acc[du * 9 + dv] += xav[t] * xbv[t + dv];
        }
        __syncthreads();
    }

#pragma unroll
    for (int q = 0; q < 81; q++) {
        float v = acc[q];
        for (int o = 16; o; o >>= 1) v += __shfl_down_sync(0xffffffffu, v, o);
        if (lane == 0) sred[wid][q] = v;
    }
    __syncthreads();
    if (tid < 81) {
        float v = 0.f;
#pragma unroll
        for (int w = 0; w < 8; w++) v += sred[w][tid];
        int u = tid / 9, vv = tid - u * 9;
        g_R[n][a][b][u][vv] = v;
        g_R[n][b][a][8 - u][8 - vv] = v;
    }
}

// ===========================================================================
// Kernel 2: P[n,(b,u,v),o] = sum_ij y[n,o,i,j]*x[n,b,i+u-2,j+v-2]  + an*d^T
// one block per (b, o-group-of-4, batch)
// ===========================================================================
__global__ __launch_bounds__(256) void scorr_kernel(const float* __restrict__ x,
                                                    const float* __restrict__ y,
                                                    const float* __restrict__ d,
                                                    const float* __restrict__ alpha,
                                                    const float* __restrict__ regp)
{
    int n  = blockIdx.y;
    int b  = blockIdx.x & 31;
    int o0 = (blockIdx.x >> 5) * 4;

    const float* __restrict__ xb = x + ((size_t)n * CI + b) * (HH * WW);
    const float* __restrict__ yb = y + ((size_t)n * CO + o0) * (HH * WW);

    __shared__ float sya[4][16][128];
    __shared__ float sxb[20][132];
    __shared__ float sred[8][100];

    int tid  = threadIdx.x;
    int ty   = tid >> 4;
    int tx   = tid & 15;
    int lane = tid & 31;
    int wid  = tid >> 5;

    float acc[100];
#pragma unroll
    for (int q = 0; q < 100; q++) acc[q] = 0.f;

    for (int s = 0; s < 8; s++) {
        int r0 = s * 16;
#pragma unroll
        for (int o = 0; o < 4; o++) {
            const float4* src = (const float4*)(yb + (size_t)o * (HH * WW) + (size_t)(r0 + ty) * WW);
            float4* dst = (float4*)(&sya[o][ty][0]);
            dst[tx * 2]     = src[tx * 2];
            dst[tx * 2 + 1] = src[tx * 2 + 1];
        }
        for (int idx = tid; idx < 20 * 132; idx += 256) {
            int rr = idx / 132, cc = idx - rr * 132;
            int gr = r0 + rr - 2, gc = cc - 2;
            float v = 0.f;
            if (gr >= 0 && gr < HH && gc >= 0 && gc < WW)
                v = xb[(size_t)gr * WW + gc];
            sxb[rr][cc] = v;
        }
        __syncthreads();

#pragma unroll
        for (int o = 0; o < 4; o++) {
            float yav[8];
#pragma unroll
            for (int t = 0; t < 8; t++) yav[t] = sya[o][ty][tx * 8 + t];
#pragma unroll
            for (int du = 0; du < 5; du++) {
                float xbv[12];
                const float4* row = (const float4*)(&sxb[ty + du][tx * 8]);
#pragma unroll
                for (int q4 = 0; q4 < 3; q4++) {
                    float4 v = row[q4];
                    xbv[q4 * 4 + 0] = v.x; xbv[q4 * 4 + 1] = v.y;
                    xbv[q4 * 4 + 2] = v.z; xbv[q4 * 4 + 3] = v.w;
                }
#pragma unroll
                for (int t = 0; t < 8; t++)
#pragma unroll
                    for (int dv = 0; dv < 5; dv++)
                        acc[o * 25 + du * 5 + dv] += yav[t] * xbv[t + dv];
            }
        }
        __syncthreads();
    }

#pragma unroll
    for (int q = 0; q < 100; q++) {
        float v = acc[q];
        for (int oo = 16; oo; oo >>= 1) v += __shfl_down_sync(0xffffffffu, v, oo);
        if (lane == 0) sred[wid][q] = v;
    }
    __syncthreads();
    if (tid < 100) {
        float v = 0.f;
#pragma unroll
        for (int w = 0; w < 8; w++) v += sred[w][tid];
        int o = tid / 25, q = tid - o * 25;
        int k = b * 25 + q;
        float an = alpha[n] * ((float)(HH * WW) * regp[0] / (float)(DS * DS * CI));
        g_P[n][k][o0 + o] = v + an * d[((size_t)n * CO + o0 + o) * KK + k];
    }
}

// ===========================================================================
// Kernel 3: expand LOWER triangle of Q from R, add ridge on diagonal
// ===========================================================================
__global__ void assembleQ_kernel(const float* __restrict__ alpha,
                                 const float* __restrict__ regp)
{
    int n  = blockIdx.y;
    int k1 = blockIdx.x;
    int a = k1 / 25, r = (k1 / 5) % 5, s = k1 % 5;
    float an = alpha[n] * ((float)(HH * WW) * regp[0] / (float)(DS * DS * CI));
    for (int k2 = threadIdx.x; k2 <= k1; k2 += 256) {
        int bb = k2 / 25, pp = (k2 / 5) % 5, tt = k2 % 5;
        float v = g_R[n][a][bb][pp - r + 4][tt - s + 4];
        if (k2 == k1) v += an;
        g_Q[n][k1][k2] = v;
    }
}

// ===========================================================================
// Cholesky: panel potrf (in shared), one block per batch
// ===========================================================================
__global__ __launch_bounds__(256) void potrf_kernel(int k0)
{
    int n = blockIdx.x;
    __shared__ float A[BS][BS + 1];
    __shared__ float sinv;
    int tid = threadIdx.x;
    int lane = tid & 31, wid = tid >> 5;

    for (int idx = tid; idx < BS * BS; idx += 256) {
        int i = idx / BS, j = idx - i * BS;
        A[i][j] = g_Q[n][k0 + i][k0 + j];
    }
    __syncthreads();

    for (int j = 0; j < BS; j++) {
        if (tid == 0) {
            float s = sqrtf(A[j][j]);
            A[j][j] = s;
            sinv = 1.0f / s;
        }
        __syncthreads();
        float inv = sinv;
        for (int i = j + 1 + tid; i < BS; i += 256) A[i][j] *= inv;
        __syncthreads();
        for (int i = j + 1 + wid; i < BS; i += 8) {
            float aij = A[i][j];
            for (int k = j + 1 + lane; k <= i; k += 32)
                A[i][k] -= aij * A[k][j];
        }
        __syncthreads();
    }

    for (int idx = tid; idx < BS * BS; idx += 256) {
        int i = idx / BS, j = idx - i * BS;
        if (j <= i) g_Q[n][k0 + i][k0 + j] = A[i][j];
    }
}

// ===========================================================================
// trsm (merged): A21 <- A21*L11^{-T}  AND  P-panel columns <- L11^{-1}*P
// warp-per-row; rows >= `rows` index the 64 P columns (transposed view).
// ===========================================================================
__global__ __launch_bounds__(256) void trsm_kernel(int k0)
{
    int n = blockIdx.y;
    int rows = KK - k0 - BS;
    __shared__ float L[BS][BS + 1];
    __shared__ float inv[BS];
    int tid = threadIdx.x;
    int lane = tid & 31, wid = tid >> 5;

    for (int idx = tid; idx < BS * BS; idx += 256) {
        int i = idx / BS, j = idx - i * BS;
        L[i][j] = (j <= i) ? g_Q[n][k0 + i][k0 + j] : 0.f;
    }
    __syncthreads();
    if (tid < BS) inv[tid] = 1.0f / L[tid][tid];
    __syncthreads();

    int ridx = blockIdx.x * 8 + wid;
    bool isP = (ridx >= rows);
    int r = 0, c = 0;
    bool active;
    if (isP) { c = ridx - rows; active = (c < CO); }
    else     { r = k0 + BS + ridx; active = true; }

    if (active) {
        float v[4];
#pragma unroll
        for (int q = 0; q < 4; q++) {
            int m = lane + 32 * q;
            if (m < BS) v[q] = isP ? g_P[n][k0 + m][c] : g_Q[n][r][k0 + m];
            else        v[q] = 0.f;
        }
        for (int j = 0; j < BS; j++) {
            int srcq = j >> 5, srclane = j & 31;
            float vj = (srcq == 0) ? v[0] : (srcq == 1) ? v[1] : (srcq == 2) ? v[2] : v[3];
            vj = __shfl_sync(0xffffffffu, vj, srclane);
            vj *= inv[j];
            if (lane == srclane) {
                if (srcq == 0) v[0] = vj; else if (srcq == 1) v[1] = vj;
                else if (srcq == 2) v[2] = vj; else v[3] = vj;
            }
#pragma unroll
            for (int q = 0; q < 4; q++) {
                int m = lane + 32 * q;
                if (m > j && m < BS) v[q] -= L[m][j] * vj;
            }
        }
#pragma unroll
        for (int q = 0; q < 4; q++) {
            int m = lane + 32 * q;
            if (m < BS) {
                if (isP) g_P[n][k0 + m][c] = v[q];
                else     g_Q[n][r][k0 + m] = v[q];
            }
        }
    }
}

// ===========================================================================
// syrk (merged): A22 -= L21*L21^T (lower tiles)  AND  P2 -= L21*Z1 (P tiles)
// ===========================================================================
__global__ __launch_bounds__(256) void syrk_kernel(int k0)
{
    int off = k0 + BS;
    int m = KK - off;
    int nt = (m + 63) >> 6;
    int ntri = nt * (nt + 1) / 2;
    int n = blockIdx.x == 0 ? blockIdx.y : blockIdx.y;  // keep simple
    n = blockIdx.y;
    int p = blockIdx.x;

    __shared__ float LA[64][21];
    __shared__ float LB[64][21];
    int tid = threadIdx.x;
    int txx = tid & 15, tyy = tid >> 4;

    int ti, tj;
    bool pmode = (p >= ntri);
    if (pmode) { ti = p - ntri; tj = -1; }
    else {
        tj = 0;
        while (p >= nt - tj) { p -= nt - tj; tj++; }
        ti = tj + p;
    }

    float c[4][4];
#pragma unroll
    for (int i = 0; i < 4; i++)
#pragma unroll
        for (int j = 0; j < 4; j++) c[i][j] = 0.f;

    int rbase = off + ti * 64;
    int cbase = pmode ? 0 : off + tj * 64;

    for (int kk = 0; kk < BS; kk += 20) {
        for (int idx = tid; idx < 64 * 20; idx += 256) {
            int rr = idx / 20, k = idx - rr * 20;
            LA[rr][k] = (rbase + rr < KK) ? g_Q[n][rbase + rr][k0 + kk + k] : 0.f;
        }
        if (pmode) {
            for (int idx = tid; idx < 20 * 64; idx += 256) {
                int k = idx >> 6, cc = idx & 63;
                LB[cc][k] = g_P[n][k0 + kk + k][cc];
            }
        } else {
            for (int idx = tid; idx < 64 * 20; idx += 256) {
                int rr = idx / 20, k = idx - rr * 20;
                LB[rr][k] = (cbase + rr < KK) ? g_Q[n][cbase + rr][k0 + kk + k] : 0.f;
            }
        }
        __syncthreads();
#pragma unroll
        for (int k = 0; k < 20; k++) {
            float ra[4], rb[4];
#pragma unroll
            for (int i = 0; i < 4; i++) ra[i] = LA[tyy * 4 + i][k];
#pragma unroll
            for (int j = 0; j < 4; j++) rb[j] = LB[txx * 4 + j][k];
#pragma unroll
            for (int i = 0; i < 4; i++)
#pragma unroll
                for (int j = 0; j < 4; j++) c[i][j] += ra[i] * rb[j];
        }
        __syncthreads();
    }
#pragma unroll
    for (int i = 0; i < 4; i++) {
        int gr = rbase + tyy * 4 + i;
        if (gr < KK) {
            if (pmode) {
#pragma unroll
                for (int j = 0; j < 4; j++)
                    g_P[n][gr][txx * 4 + j] -= c[i][j];
            } else {
#pragma unroll
                for (int j = 0; j < 4; j++) {
                    int gc = cbase + txx * 4 + j;
                    if (gc < KK) g_Q[n][gr][gc] -= c[i][j];
                }
            }
        }
    }
}

// ===========================================================================
// backward: solve L_ii^T * D_i = Z_i   (warp per column)
// ===========================================================================
__global__ __launch_bounds__(1024) void trsv_bwd_kernel(int k0)
{
    int n = blockIdx.x;
    int chalf = blockIdx.y;
    __shared__ float L[BS][BS + 1];
    __shared__ float inv[BS];
    int tid = threadIdx.x;
    int lane = tid & 31, w = tid >> 5;

    for (int idx = tid; idx < BS * BS; idx += 1024) {
        int i = idx / BS, j = idx - i * BS;
        L[i][j] = (j <= i) ? g_Q[n][k0 + i][k0 + j] : 0.f;
    }
    __syncthreads();
    if (tid < BS) inv[tid] = 1.0f / L[tid][tid];
    __syncthreads();

    int c = chalf * 32 + w;
    float v[4];
#pragma unroll
    for (int q = 0; q < 4; q++) {
        int m = lane + 32 * q;
        v[q] = (m < BS) ? g_P[n][k0 + m][c] : 0.f;
    }
    for (int j = BS - 1; j >= 0; j--) {
        int srcq = j >> 5, srclane = j & 31;
        float vj = (srcq == 0) ? v[0] : (srcq == 1) ? v[1] : (srcq == 2) ? v[2] : v[3];
        vj = __shfl_sync(0xffffffffu, vj, srclane);
        vj *= inv[j];
        if (lane == srclane) {
            if (srcq == 0) v[0] = vj; else if (srcq == 1) v[1] = vj;
            else if (srcq == 2) v[2] = vj; else v[3] = vj;
        }
#pragma unroll
        for (int q = 0; q < 4; q++) {
            int m = lane + 32 * q;
            if (m < j) v[q] -= L[j][m] * vj;
        }
    }
#pragma unroll
    for (int q = 0; q < 4; q++) {
        int m = lane + 32 * q;
        if (m < BS) g_P[n][k0 + m][c] = v[q];
    }
}

// backward update: Z[0:k0, :] -= L[k0:k0+100, 0:k0]^T * D[k0:k0+100, :]
__global__ __launch_bounds__(256) void bsolve_update_kernel(int k0)
{
    int n = blockIdx.y;
    int rbase = blockIdx.x * 64;

    __shared__ float AT[20][65];
    __shared__ float BB[20][65];
    int tid = threadIdx.x;
    int txx = tid & 15, tyy = tid >> 4;

    float c[4][4];
#pragma unroll
    for (int i = 0; i < 4; i++)
#pragma unroll
        for (int j = 0; j < 4; j++) c[i][j] = 0.f;

    for (int kk = 0; kk < BS; kk += 20) {
        for (int idx = tid; idx < 20 * 64; idx += 256) {
            int k = idx >> 6, rl = idx & 63;
            AT[k][rl] = g_Q[n][k0 + kk + k][rbase + rl];
        }
        for (int idx = tid; idx < 20 * 64; idx += 256) {
            int k = idx >> 6, cc = idx & 63;
            BB[k][cc] = g_P[n][k0 + kk + k][cc];
        }
        __syncthreads();
#pragma unroll
        for (int k = 0; k < 20; k++) {
            float ra[4], rb[4];
#pragma unroll
            for (int i = 0; i < 4; i++) ra[i] = AT[k][tyy * 4 + i];
#pragma unroll
            for (int j = 0; j < 4; j++) rb[j] = BB[k][txx * 4 + j];
#pragma unroll
            for (int i = 0; i < 4; i++)
#pragma unroll
                for (int j = 0; j < 4; j++) c[i][j] += ra[i] * rb[j];
        }
        __syncthreads();
    }
#pragma unroll
    for (int i = 0; i < 4; i++) {
        int gr = rbase + tyy * 4 + i;
        if (gr < k0) {
#pragma unroll
            for (int j = 0; j < 4; j++)
                g_P[n][gr][txx * 4 + j] -= c[i][j];
        }
    }
}

// final transpose: out[n][o][k] = P[n][k][o]   (32x32 smem tiles)
__global__ __launch_bounds__(256) void output_kernel(float* __restrict__ out)
{
    __shared__ float t[32][33];
    int n  = blockIdx.z;
    int kb = blockIdx.x * 32;
    int ob = blockIdx.y * 32;
    int tx = threadIdx.x & 31, ty4 = threadIdx.x >> 5;  // 32 x 8

    for (int i = ty4; i < 32; i += 8)
        t[i][tx] = g_P[n][kb + i][ob + tx];
    __syncthreads();
    for (int i = ty4; i < 32; i += 8)
        out[((size_t)n * CO + ob + i) * KK + kb + tx] = t[tx][i];
}

// ===========================================================================
extern "C" void kernel_launch(void* const* d_in, const int* in_sizes, int n_in,
                              void* d_out, int out_size)
{
    const float* x     = (const float*)d_in[0];   // (16,1,32,128,128)
    const float* d     = (const float*)d_in[1];   // (16,64,32,5,5)
    const float* y     = (const float*)d_in[2];   // (16,64,1,128,128)
    const float* alpha = (const float*)d_in[3];   // (16,1,1,1)
    const float* regp  = (const float*)d_in[4];   // scalar

    gram_kernel <<<dim3(528, NBATCH), 256>>>(x);
    scorr_kernel<<<dim3(512, NBATCH), 256>>>(x, y, d, alpha, regp);
    assembleQ_kernel<<<dim3(KK, NBATCH), 256>>>(alpha, regp);

    // blocked Cholesky with fused forward solve
    for (int s = 0; s < NSTEP; s++) {
        int k0 = s * BS;
        potrf_kernel<<<NBATCH, 256>>>(k0);
        int rows = KK - k0 - BS;
        trsm_kernel<<<dim3((rows + CO + 7) / 8, NBATCH), 256>>>(k0);
        if (rows > 0) {
            int nt = (rows + 63) / 64;
            int tiles = nt * (nt + 1) / 2 + nt;   // lower tiles + P tiles
            syrk_kernel<<<dim3(tiles, NBATCH), 256>>>(k0);
        }
    }
    // backward substitution
    for (int s = NSTEP - 1; s >= 0; s--) {
        int k0 = s * BS;
        trsv_bwd_kernel<<<dim3(NBATCH, 2), 1024>>>(k0);
        if (k0 > 0)
            bsolve_update_kernel<<<dim3((k0 + 63) / 64, NBATCH), 256>>>(k0);
    }

    output_kernel<<<dim3(KK / 32, CO / 32, NBATCH), 256>>>((float*)d_out);
}

// round 7
// speedup vs baseline: 1.1246x; 1.0167x over previous
#include <cuda_runtime.h>
#include <cuda_bf16.h>
#include <math.h>

#define NBATCH 16
#define CI 32
#define CO 64
#define HH 128
#define WW 128
#define DS 5
#define KK 800     // CI*DS*DS
#define BS 100     // Cholesky panel
#define SB 20      // potrf sub-block
#define NSTEP 8    // KK/BS

// ---------------- scratch ----------
__device__ float g_R[NBATCH][CI][CI][9][9];       // channel autocorrelation
__device__ float g_Q[NBATCH][KK][KK];             // Gram -> Cholesky factor (lower)
__device__ float g_P[NBATCH][KK][CO];             // RHS -> z -> solution
__device__ float g_Linv[NSTEP][NBATCH][BS][BS];   // per-step panel inverse (upper=0)

// ===========================================================================
// Kernel 1: R[n,a,b,du,dv] = sum_ij x[n,a,i,j]*x[n,b,i+du-4,j+dv-4]
// ===========================================================================
__global__ __launch_bounds__(256) void gram_kernel(const float* __restrict__ x)
{
    int n = blockIdx.y;
    int p = blockIdx.x;
    int a = 0, rem = p;
    while (rem >= CI - a) { rem -= CI - a; a++; }
    int b = a + rem;

    const float* __restrict__ xa = x + ((size_t)n * CI + a) * (HH * WW);
    const float* __restrict__ xb = x + ((size_t)n * CI + b) * (HH * WW);

    __shared__ float sxa[16][128];
    __shared__ float sxb[24][136];
    __shared__ float sred[8][81];

    int tid  = threadIdx.x;
    int ty   = tid >> 4;
    int tx   = tid & 15;
    int lane = tid & 31;
    int wid  = tid >> 5;

    float acc[81];
#pragma unroll
    for (int q = 0; q < 81; q++) acc[q] = 0.f;

    for (int s = 0; s < 8; s++) {
        int r0 = s * 16;
        {
            const float4* src = (const float4*)(xa + (size_t)(r0 + ty) * WW);
            float4* dst = (float4*)(&sxa[ty][0]);
            dst[tx * 2]     = src[tx * 2];
            dst[tx * 2 + 1] = src[tx * 2 + 1];
        }
        for (int idx = tid; idx < 24 * 136; idx += 256) {
            int rr = idx / 136, cc = idx - rr * 136;
            int gr = r0 + rr - 4, gc = cc - 4;
            float v = 0.f;
            if (gr >= 0 && gr < HH && gc >= 0 && gc < WW)
                v = xb[(size_t)gr * WW + gc];
            sxb[rr][cc] = v;
        }
        __syncthreads();

        float xav[8];
#pragma unroll
        for (int t = 0; t < 8; t++) xav[t] = sxa[ty][tx * 8 + t];

#pragma unroll
        for (int du = 0; du < 9; du++) {
            float xbv[16];
            const float4* row = (const float4*)(&sxb[ty + du][tx * 8]);
#pragma unroll
            for (int q4 = 0; q4 < 4; q4++) {
                float4 v = row[q4];
                xbv[q4 * 4 + 0] = v.x; xbv[q4 * 4 + 1] = v.y;
                xbv[q4 * 4 + 2] = v.z; xbv[q4 * 4 + 3] = v.w;
            }
#pragma unroll
            for (int t = 0; t < 8; t++)
#pragma unroll
                for (int dv = 0; dv < 9; dv++)
                    acc[du * 9 + dv] += xav[t] * xbv[t + dv];
        }
        __syncthreads();
    }

#pragma unroll
    for (int q = 0; q < 81; q++) {
        float v = acc[q];
        for (int o = 16; o; o >>= 1) v += __shfl_down_sync(0xffffffffu, v, o);
        if (lane == 0) sred[wid][q] = v;
    }
    __syncthreads();
    if (tid < 81) {
        float v = 0.f;
#pragma unroll
        for (int w = 0; w < 8; w++) v += sred[w][tid];
        int u = tid / 9, vv = tid - u * 9;
        g_R[n][a][b][u][vv] = v;
        g_R[n][b][a][8 - u][8 - vv] = v;
    }
}

// ===========================================================================
// Kernel 2: P[n,(b,u,v),o] = sum_ij y[n,o,i,j]*x[n,b,i+u-2,j+v-2]  + an*d^T
// ===========================================================================
__global__ __launch_bounds__(256) void scorr_kernel(const float* __restrict__ x,
                                                    const float* __restrict__ y,
                                                    const float* __restrict__ d,
                                                    const float* __restrict__ alpha,
                                                    const float* __restrict__ regp)
{
    int n  = blockIdx.y;
    int b  = blockIdx.x & 31;
    int o0 = (blockIdx.x >> 5) * 4;

    const float* __restrict__ xb = x + ((size_t)n * CI + b) * (HH * WW);
    const float* __restrict__ yb = y + ((size_t)n * CO + o0) * (HH * WW);

    __shared__ float sya[4][16][128];
    __shared__ float sxb[20][132];
    __shared__ float sred[8][100];

    int tid  = threadIdx.x;
    int ty   = tid >> 4;
    int tx   = tid & 15;
    int lane = tid & 31;
    int wid  = tid >> 5;

    float acc[100];
#pragma unroll
    for (int q = 0; q < 100; q++) acc[q] = 0.f;

    for (int s = 0; s < 8; s++) {
        int r0 = s * 16;
#pragma unroll
        for (int o = 0; o < 4; o++) {
            const float4* src = (const float4*)(yb + (size_t)o * (HH * WW) + (size_t)(r0 + ty) * WW);
            float4* dst = (float4*)(&sya[o][ty][0]);
            dst[tx * 2]     = src[tx * 2];
            dst[tx * 2 + 1] = src[tx * 2 + 1];
        }
        for (int idx = tid; idx < 20 * 132; idx += 256) {
            int rr = idx / 132, cc = idx - rr * 132;
            int gr = r0 + rr - 2, gc = cc - 2;
            float v = 0.f;
            if (gr >= 0 && gr < HH && gc >= 0 && gc < WW)
                v = xb[(size_t)gr * WW + gc];
            sxb[rr][cc] = v;
        }
        __syncthreads();

#pragma unroll
        for (int o = 0; o < 4; o++) {
            float yav[8];
#pragma unroll
            for (int t = 0; t < 8; t++) yav[t] = sya[o][ty][tx * 8 + t];
#pragma unroll
            for (int du = 0; du < 5; du++) {
                float xbv[12];
                const float4* row = (const float4*)(&sxb[ty + du][tx * 8]);
#pragma unroll
                for (int q4 = 0; q4 < 3; q4++) {
                    float4 v = row[q4];
                    xbv[q4 * 4 + 0] = v.x; xbv[q4 * 4 + 1] = v.y;
                    xbv[q4 * 4 + 2] = v.z; xbv[q4 * 4 + 3] = v.w;
                }
#pragma unroll
                for (int t = 0; t < 8; t++)
#pragma unroll
                    for (int dv = 0; dv < 5; dv++)
                        acc[o * 25 + du * 5 + dv] += yav[t] * xbv[t + dv];
            }
        }
        __syncthreads();
    }

#pragma unroll
    for (int q = 0; q < 100; q++) {
        float v = acc[q];
        for (int oo = 16; oo; oo >>= 1) v += __shfl_down_sync(0xffffffffu, v, oo);
        if (lane == 0) sred[wid][q] = v;
    }
    __syncthreads();
    if (tid < 100) {
        float v = 0.f;
#pragma unroll
        for (int w = 0; w < 8; w++) v += sred[w][tid];
        int o = tid / 25, q = tid - o * 25;
        int k = b * 25 + q;
        float an = alpha[n] * ((float)(HH * WW) * regp[0] / (float)(DS * DS * CI));
        g_P[n][k][o0 + o] = v + an * d[((size_t)n * CO + o0 + o) * KK + k];
    }
}

// ===========================================================================
// Kernel 3: expand LOWER triangle of Q from R, add ridge on diagonal
// ===========================================================================
__global__ void assembleQ_kernel(const float* __restrict__ alpha,
                                 const float* __restrict__ regp)
{
    int n  = blockIdx.y;
    int k1 = blockIdx.x;
    int a = k1 / 25, r = (k1 / 5) % 5, s = k1 % 5;
    float an = alpha[n] * ((float)(HH * WW) * regp[0] / (float)(DS * DS * CI));
    for (int k2 = threadIdx.x; k2 <= k1; k2 += 256) {
        int bb = k2 / 25, pp = (k2 / 5) % 5, tt = k2 % 5;
        float v = g_R[n][a][bb][pp - r + 4][tt - s + 4];
        if (k2 == k1) v += an;
        g_Q[n][k1][k2] = v;
    }
}

// ===========================================================================
// potrf v3: sub-blocked 100x100 factor + explicit inverse of L11.
// dynamic smem: A[100][101] + V[100][101]  (80800 B)
// ===========================================================================
__global__ __launch_bounds__(256) void potrf_kernel(int k0, int s)
{
    int n = blockIdx.x;
    extern __shared__ float sh[];
    float (*A)[BS + 1] = (float(*)[BS + 1])sh;
    float (*V)[BS + 1] = (float(*)[BS + 1])(sh + BS * (BS + 1));
    __shared__ float dinv[BS];

    int tid  = threadIdx.x;
    int lane = tid & 31;
    int wid  = tid >> 5;

    for (int idx = tid; idx < BS * BS; idx += 256) {
        int i = idx / BS, j = idx - i * BS;
        A[i][j] = g_Q[n][k0 + i][k0 + j];
    }
    __syncthreads();

    // -------- factorization in 20-wide sub-blocks --------
    for (int p = 0; p < BS / SB; p++) {
        int c0 = p * SB;
        // (a) warp 0 factors diag 20x20 via shfl
        if (wid == 0) {
            int i = lane;
            for (int j = 0; j < SB; j++) {
                int gj = c0 + j;
                if (lane == 0) {
                    float s0 = sqrtf(A[gj][gj]);
                    A[gj][gj] = s0;
                    dinv[gj]  = 1.0f / s0;
                }
                __syncwarp();
                float dv  = dinv[gj];
                float aij = 0.f;
                if (i > j && i < SB) aij = A[c0 + i][gj] * dv;
                for (int k = j + 1; k < SB; k++) {
                    float akj = __shfl_sync(0xffffffffu, aij, k);
                    if (i > j && i < SB && k <= i)
                        A[c0 + i][c0 + k] -= aij * akj;
                }
                if (i > j && i < SB) A[c0 + i][gj] = aij;
                __syncwarp();
            }
        }
        __syncthreads();

        // (b) thread-per-row panel trsm: rows c0+SB..99
        int r = c0 + SB + tid;
        if (r < BS) {
            float v[SB];
#pragma unroll
            for (int j = 0; j < SB; j++) v[j] = A[r][c0 + j];
#pragma unroll
            for (int j = 0; j < SB; j++) {
                float t = v[j];
                for (int m = 0; m < j; m++) t -= A[c0 + j][c0 + m] * v[m];
                v[j] = t * dinv[c0 + j];
            }
#pragma unroll
            for (int j = 0; j < SB; j++) A[r][c0 + j] = v[j];
        }
        __syncthreads();

        // (c) rank-20 trailing update (full square; upper garbage unused)
        int m = BS - c0 - SB;
        if (m > 0) {
            int tr = tid >> 4, tc = tid & 15;
            float c[5][5];
#pragma unroll
            for (int i = 0; i < 5; i++)
#pragma unroll
                for (int j = 0; j < 5; j++) c[i][j] = 0.f;
#pragma unroll
            for (int k = 0; k < SB; k++) {
                float ra[5], rb[5];
#pragma unroll
                for (int ii = 0; ii < 5; ii++) {
                    int row = c0 + SB + tr + ii * 16;
                    ra[ii] = (row < BS) ? A[row][c0 + k] : 0.f;
                }
#pragma unroll
                for (int jj = 0; jj < 5; jj++) {
                    int col = c0 + SB + tc + jj * 16;
                    rb[jj] = (col < BS) ? A[col][c0 + k] : 0.f;
                }
#pragma unroll
                for (int ii = 0; ii < 5; ii++)
#pragma unroll
                    for (int jj = 0; jj < 5; jj++)
                        c[ii][jj] += ra[ii] * rb[jj];
            }
#pragma unroll
            for (int ii = 0; ii < 5; ii++) {
                int row = c0 + SB + tr + ii * 16;
                if (row < BS) {
#pragma unroll
                    for (int jj = 0; jj < 5; jj++) {
                        int col = c0 + SB + tc + jj * 16;
                        if (col < BS) A[row][col] -= c[ii][jj];
                    }
                }
            }
        }
        __syncthreads();
    }

    // -------- blocked inverse: V = L^{-1} (lower), 5 row sweeps --------
    for (int I = 0; I < BS / SB; I++) {
        int base = I * SB;
        // (1) partial sums from previous row blocks
        for (int idx = tid; idx < SB * base; idx += 256) {
            int jj = idx / base, c = idx - jj * base;
            float w = 0.f;
            for (int m = c; m < base; m++)
                w += A[base + jj][m] * V[m][c];
            V[base + jj][c] = w;
        }
        __syncthreads();
        // (2) thread-per-column triangular solve within block
        if (tid < base + SB) {
            int c = tid;
#pragma unroll 1
            for (int jj = 0; jj < SB; jj++) {
                int r = base + jj;
                float t = (c == r ? 1.f : 0.f) - (c < base ? V[r][c] : 0.f);
                int mstart = (c >= base) ? (c - base) : 0;
                for (int mm = mstart; mm < jj; mm++)
                    t -= A[r][base + mm] * V[base + mm][c];
                V[r][c] = t * dinv[r];
            }
        }
        __syncthreads();
    }

    // -------- writeback --------
    for (int idx = tid; idx < BS * BS; idx += 256) {
        int i = idx / BS, j = idx - i * BS;
        if (j <= i) g_Q[n][k0 + i][k0 + j] = A[i][j];
        g_Linv[s][n][i][j] = (j <= i) ? V[i][j] : 0.f;
    }
}

// ===========================================================================
// trsm as GEMM against Linv:
//   blocks p<rowTiles:  A21(64 rows) <- A21 * Linv^T
//   block  p==rowTiles: Z1 <- Linv * P1
// dynamic smem: Li[100][101] + tile (max 100*65)  (66400 B)
// ===========================================================================
__global__ __launch_bounds__(256) void trsm_gemm(int k0, int s)
{
    int n = blockIdx.y;
    int p = blockIdx.x;
    int rows = KK - k0 - BS;
    int rowTiles = (rows + 63) >> 6;

    extern __shared__ float sh[];
    float (*Li)[BS + 1] = (float(*)[BS + 1])sh;

    int tid = threadIdx.x;
    int tr = tid >> 4, tc = tid & 15;

    for (int idx = tid; idx < BS * BS; idx += 256) {
        int i = idx / BS, j = idx - i * BS;
        Li[i][j] = g_Linv[s][n][i][j];
    }

    if (p < rowTiles) {
        float (*Ta)[BS + 1] = (float(*)[BS + 1])(sh + BS * (BS + 1));
        int rbase = k0 + BS + p * 64;
        for (int idx = tid; idx < 64 * BS; idx += 256) {
            int rr = idx / BS, k = idx - rr * BS;
            Ta[rr][k] = (rbase + rr < KK) ? g_Q[n][rbase + rr][k0 + k] : 0.f;
        }
        __syncthreads();

        float c[4][7];
#pragma unroll
        for (int i = 0; i < 4; i++)
#pragma unroll
            for (int j = 0; j < 7; j++) c[i][j] = 0.f;
#pragma unroll 4
        for (int k = 0; k < BS; k++) {
            float ra[4], rb[7];
#pragma unroll
            for (int ii = 0; ii < 4; ii++) ra[ii] = Ta[tr + 16 * ii][k];
#pragma unroll
            for (int jj = 0; jj < 7; jj++) {
                int j = tc + 16 * jj;
                rb[jj] = (j < BS) ? Li[j][k] : 0.f;
            }
#pragma unroll
            for (int ii = 0; ii < 4; ii++)
#pragma unroll
                for (int jj = 0; jj < 7; jj++)
                    c[ii][jj] += ra[ii] * rb[jj];
        }
#pragma unroll
        for (int ii = 0; ii < 4; ii++) {
            int gr = rbase + tr + 16 * ii;
            if (gr < KK) {
#pragma unroll
                for (int jj = 0; jj < 7; jj++) {
                    int j = tc + 16 * jj;
                    if (j < BS) g_Q[n][gr][k0 + j] = c[ii][jj];
                }
            }
        }
    } else {
        float (*Tp)[CO + 1] = (float(*)[CO + 1])(sh + BS * (BS + 1));
        for (int idx = tid; idx < BS * CO; idx += 256) {
            int k = idx >> 6, cc = idx & 63;
            Tp[k][cc] = g_P[n][k0 + k][cc];
        }
        __syncthreads();

        float c[7][4];
#pragma unroll
        for (int i = 0; i < 7; i++)
#pragma unroll
            for (int j = 0; j < 4; j++) c[i][j] = 0.f;
#pragma unroll 4
        for (int k = 0; k < BS; k++) {
            float ra[7], rb[4];
#pragma unroll
            for (int ii = 0; ii < 7; ii++) {
                int i = tr + 16 * ii;
                ra[ii] = (i < BS) ? Li[i][k] : 0.f;
            }
#pragma unroll
            for (int jj = 0; jj < 4; jj++) rb[jj] = Tp[k][tc + 16 * jj];
#pragma unroll
            for (int ii = 0; ii < 7; ii++)
#pragma unroll
                for (int jj = 0; jj < 4; jj++)
                    c[ii][jj] += ra[ii] * rb[jj];
        }
#pragma unroll
        for (int ii = 0; ii < 7; ii++) {
            int i = tr + 16 * ii;
            if (i < BS) {
#pragma unroll
                for (int jj = 0; jj < 4; jj++)
                    g_P[n][k0 + i][tc + 16 * jj] = c[ii][jj];
            }
        }
    }
}

// ===========================================================================
// syrk (merged): A22 -= L21*L21^T (lower tiles)  AND  P2 -= L21*Z1 (P tiles)
// ===========================================================================
__global__ __launch_bounds__(256) void syrk_kernel(int k0)
{
    int off = k0 + BS;
    int m = KK - off;
    int nt = (m + 63) >> 6;
    int ntri = nt * (nt + 1) / 2;
    int n = blockIdx.y;
    int p = blockIdx.x;

    __shared__ float LA[64][21];
    __shared__ float LB[64][21];
    int tid = threadIdx.x;
    int txx = tid & 15, tyy = tid >> 4;

    int ti, tj;
    bool pmode = (p >= ntri);
    if (pmode) { ti = p - ntri; tj = -1; }
    else {
        tj = 0;
        while (p >= nt - tj) { p -= nt - tj; tj++; }
        ti = tj + p;
    }

    float c[4][4];
#pragma unroll
    for (int i = 0; i < 4; i++)
#pragma unroll
        for (int j = 0; j < 4; j++) c[i][j] = 0.f;

    int rbase = off + ti * 64;
    int cbase = pmode ? 0 : off + tj * 64;

    for (int kk = 0; kk < BS; kk += 20) {
        for (int idx = tid; idx < 64 * 20; idx += 256) {
            int rr = idx / 20, k = idx - rr * 20;
            LA[rr][k] = (rbase + rr < KK) ? g_Q[n][rbase + rr][k0 + kk + k] : 0.f;
        }
        if (pmode) {
            for (int idx = tid; idx < 20 * 64; idx += 256) {
                int k = idx >> 6, cc = idx & 63;
                LB[cc][k] = g_P[n][k0 + kk + k][cc];
            }
        } else {
            for (int idx = tid; idx < 64 * 20; idx += 256) {
                int rr = idx / 20, k = idx - rr * 20;
                LB[rr][k] = (cbase + rr < KK) ? g_Q[n][cbase + rr][k0 + kk + k] : 0.f;
            }
        }
        __syncthreads();
#pragma unroll
        for (int k = 0; k < 20; k++) {
            float ra[4], rb[4];
#pragma unroll
            for (int i = 0; i < 4; i++) ra[i] = LA[tyy * 4 + i][k];
#pragma unroll
            for (int j = 0; j < 4; j++) rb[j] = LB[txx * 4 + j][k];
#pragma unroll
            for (int i = 0; i < 4; i++)
#pragma unroll
                for (int j = 0; j < 4; j++) c[i][j] += ra[i] * rb[j];
        }
        __syncthreads();
    }
#pragma unroll
    for (int i = 0; i < 4; i++) {
        int gr = rbase + tyy * 4 + i;
        if (gr < KK) {
            if (pmode) {
#pragma unroll
                for (int j = 0; j < 4; j++)
                    g_P[n][gr][txx * 4 + j] -= c[i][j];
            } else {
#pragma unroll
                for (int j = 0; j < 4; j++) {
                    int gc = cbase + txx * 4 + j;
                    if (gc < KK) g_Q[n][gr][gc] -= c[i][j];
                }
            }
        }
    }
}

// ===========================================================================
// backward diag solve as GEMM: Z_panel <- Linv^T * Z_panel
// grid (2, NBATCH): column halves. dyn smem Li[100][101]+Zp[100][33] (53600 B)
// ===========================================================================
__global__ __launch_bounds__(256) void bwd_gemm(int k0, int s)
{
    int n = blockIdx.y;
    int half = blockIdx.x;

    extern __shared__ float sh[];
    float (*Li)[BS + 1] = (float(*)[BS + 1])sh;
    float (*Zp)[33]     = (float(*)[33])(sh + BS * (BS + 1));

    int tid = threadIdx.x;
    int tr = tid >> 4, tc = tid & 15;

    for (int idx = tid; idx < BS * BS; idx += 256) {
        int i = idx / BS, j = idx - i * BS;
        Li[i][j] = g_Linv[s][n][i][j];
    }
    for (int idx = tid; idx < BS * 32; idx += 256) {
        int k = idx >> 5, cc = idx & 31;
        Zp[k][cc] = g_P[n][k0 + k][half * 32 + cc];
    }
    __syncthreads();

    float c[7][2];
#pragma unroll
    for (int i = 0; i < 7; i++)
#pragma unroll
        for (int j = 0; j < 2; j++) c[i][j] = 0.f;
#pragma unroll 4
    for (int k = 0; k < BS; k++) {
        float ra[7], rb[2];
#pragma unroll
        for (int ii = 0; ii < 7; ii++) {
            int i = tr + 16 * ii;
            ra[ii] = (i < BS) ? Li[k][i] : 0.f;
        }
#pragma unroll
        for (int jj = 0; jj < 2; jj++) rb[jj] = Zp[k][tc + 16 * jj];
#pragma unroll
        for (int ii = 0; ii < 7; ii++)
#pragma unroll
            for (int jj = 0; jj < 2; jj++)
                c[ii][jj] += ra[ii] * rb[jj];
    }
#pragma unroll
    for (int ii = 0; ii < 7; ii++) {
        int i = tr + 16 * ii;
        if (i < BS) {
#pragma unroll
            for (int jj = 0; jj < 2; jj++)
                g_P[n][k0 + i][half * 32 + tc + 16 * jj] = c[ii][jj];
        }
    }
}

// backward update: Z[0:k0, :] -= L[k0:k0+100, 0:k0]^T * D[k0:k0+100, :]
__global__ __launch_bounds__(256) void bsolve_update_kernel(int k0)
{
    int n = blockIdx.y;
    int rbase = blockIdx.x * 64;

    __shared__ float AT[20][65];
    __shared__ float BB[20][65];
    int tid = threadIdx.x;
    int txx = tid & 15, tyy = tid >> 4;

    float c[4][4];
#pragma unroll
    for (int i = 0; i < 4; i++)
#pragma unroll
        for (int j = 0; j < 4; j++) c[i][j] = 0.f;

    for (int kk = 0; kk < BS; kk += 20) {
        for (int idx = tid; idx < 20 * 64; idx += 256) {
            int k = idx >> 6, rl = idx & 63;
            AT[k][rl] = g_Q[n][k0 + kk + k][rbase + rl];
        }
        for (int idx = tid; idx < 20 * 64; idx += 256) {
            int k = idx >> 6, cc = idx & 63;
            BB[k][cc] = g_P[n][k0 + kk + k][cc];
        }
        __syncthreads();
#pragma unroll
        for (int k = 0; k < 20; k++) {
            float ra[4], rb[4];
#pragma unroll
            for (int i = 0; i < 4; i++) ra[i] = AT[k][tyy * 4 + i];
#pragma unroll
            for (int j = 0; j < 4; j++) rb[j] = BB[k][txx * 4 + j];
#pragma unroll
            for (int i = 0; i < 4; i++)
#pragma unroll
                for (int j = 0; j < 4; j++) c[i][j] += ra[i] * rb[j];
        }
        __syncthreads();
    }
#pragma unroll
    for (int i = 0; i < 4; i++) {
        int gr = rbase + tyy * 4 + i;
        if (gr < k0) {
#pragma unroll
            for (int j = 0; j < 4; j++)
                g_P[n][gr][txx * 4 + j] -= c[i][j];
        }
    }
}

// final transpose: out[n][o][k] = P[n][k][o]
__global__ __launch_bounds__(256) void output_kernel(float* __restrict__ out)
{
    __shared__ float t[32][33];
    int n  = blockIdx.z;
    int kb = blockIdx.x * 32;
    int ob = blockIdx.y * 32;
    int tx = threadIdx.x & 31, ty4 = threadIdx.x >> 5;

    for (int i = ty4; i < 32; i += 8)
        t[i][tx] = g_P[n][kb + i][ob + tx];
    __syncthreads();
    for (int i = ty4; i < 32; i += 8)
        out[((size_t)n * CO + ob + i) * KK + kb + tx] = t[tx][i];
}

// ===========================================================================
extern "C" void kernel_launch(void* const* d_in, const int* in_sizes, int n_in,
                              void* d_out, int out_size)
{
    const float* x     = (const float*)d_in[0];
    const float* d     = (const float*)d_in[1];
    const float* y     = (const float*)d_in[2];
    const float* alpha = (const float*)d_in[3];
    const float* regp  = (const float*)d_in[4];

    static int attr_done = 0;
    if (!attr_done) {
        cudaFuncSetAttribute(potrf_kernel, cudaFuncAttributeMaxDynamicSharedMemorySize, 2 * BS * (BS + 1) * 4);
        cudaFuncSetAttribute(trsm_gemm,    cudaFuncAttributeMaxDynamicSharedMemorySize, (BS * (BS + 1) + BS * (CO + 1)) * 4);
        cudaFuncSetAttribute(bwd_gemm,     cudaFuncAttributeMaxDynamicSharedMemorySize, (BS * (BS + 1) + BS * 33) * 4);
        attr_done = 1;
    }

    gram_kernel <<<dim3(528, NBATCH), 256>>>(x);
    scorr_kernel<<<dim3(512, NBATCH), 256>>>(x, y, d, alpha, regp);
    assembleQ_kernel<<<dim3(KK, NBATCH), 256>>>(alpha, regp);

    // blocked Cholesky with fused forward solve
    for (int s = 0; s < NSTEP; s++) {
        int k0 = s * BS;
        potrf_kernel<<<NBATCH, 256, 2 * BS * (BS + 1) * 4>>>(k0, s);
        int rows = KK - k0 - BS;
        int rowTiles = (rows + 63) / 64;
        trsm_gemm<<<dim3(rowTiles + 1, NBATCH), 256, (BS * (BS + 1) + BS * (CO + 1)) * 4>>>(k0, s);
        if (rows > 0) {
            int nt = (rows + 63) / 64;
            int tiles = nt * (nt + 1) / 2 + nt;
            syrk_kernel<<<dim3(tiles, NBATCH), 256>>>(k0);
        }
    }
    // backward substitution
    for (int s = NSTEP - 1; s >= 0; s--) {
        int k0 = s * BS;
        bwd_gemm<<<dim3(2, NBATCH), 256, (BS * (BS + 1) + BS * 33) * 4>>>(k0, s);
        if (k0 > 0)
            bsolve_update_kernel<<<dim3((k0 + 63) / 64, NBATCH), 256>>>(k0);
    }

    output_kernel<<<dim3(KK / 32, CO / 32, NBATCH), 256>>>((float*)d_out);
}

// round 8
// speedup vs baseline: 1.3572x; 1.2069x over previous
#include <cuda_runtime.h>
#include <cuda_bf16.h>
#include <math.h>

#define NBATCH 16
#define CI 32
#define CO 64
#define HH 128
#define WW 128
#define DS 5
#define KK 800     // CI*DS*DS
#define BS 100     // Cholesky panel
#define SB 20      // potrf sub-block
#define NSTEP 8    // KK/BS

// ---------------- scratch ----------
__device__ float g_R[NBATCH][CI][CI][9][9];       // channel autocorrelation
__device__ float g_Q[NBATCH][KK][KK];             // Gram -> Cholesky factor (lower)
__device__ float g_P[NBATCH][KK][CO];             // RHS -> z -> solution
__device__ float g_Linv[NSTEP][NBATCH][BS][BS];   // per-step panel inverse (upper=0)

// ===========================================================================
// Kernel 1: R[n,a,b,du,dv] = sum_ij x[n,a,i,j]*x[n,b,i+du-4,j+dv-4]
// ===========================================================================
__global__ __launch_bounds__(256) void gram_kernel(const float* __restrict__ x)
{
    int n = blockIdx.y;
    int p = blockIdx.x;
    int a = 0, rem = p;
    while (rem >= CI - a) { rem -= CI - a; a++; }
    int b = a + rem;

    const float* __restrict__ xa = x + ((size_t)n * CI + a) * (HH * WW);
    const float* __restrict__ xb = x + ((size_t)n * CI + b) * (HH * WW);

    __shared__ float sxa[16][128];
    __shared__ float sxb[24][136];
    __shared__ float sred[8][81];

    int tid  = threadIdx.x;
    int ty   = tid >> 4;
    int tx   = tid & 15;
    int lane = tid & 31;
    int wid  = tid >> 5;

    float acc[81];
#pragma unroll
    for (int q = 0; q < 81; q++) acc[q] = 0.f;

    for (int s = 0; s < 8; s++) {
        int r0 = s * 16;
        {
            const float4* src = (const float4*)(xa + (size_t)(r0 + ty) * WW);
            float4* dst = (float4*)(&sxa[ty][0]);
            dst[tx * 2]     = src[tx * 2];
            dst[tx * 2 + 1] = src[tx * 2 + 1];
        }
        for (int idx = tid; idx < 24 * 136; idx += 256) {
            int rr = idx / 136, cc = idx - rr * 136;
            int gr = r0 + rr - 4, gc = cc - 4;
            float v = 0.f;
            if (gr >= 0 && gr < HH && gc >= 0 && gc < WW)
                v = xb[(size_t)gr * WW + gc];
            sxb[rr][cc] = v;
        }
        __syncthreads();

        float xav[8];
#pragma unroll
        for (int t = 0; t < 8; t++) xav[t] = sxa[ty][tx * 8 + t];

#pragma unroll
        for (int du = 0; du < 9; du++) {
            float xbv[16];
            const float4* row = (const float4*)(&sxb[ty + du][tx * 8]);
#pragma unroll
            for (int q4 = 0; q4 < 4; q4++) {
                float4 v = row[q4];
                xbv[q4 * 4 + 0] = v.x; xbv[q4 * 4 + 1] = v.y;
                xbv[q4 * 4 + 2] = v.z; xbv[q4 * 4 + 3] = v.w;
            }
#pragma unroll
            for (int t = 0; t < 8; t++)
#pragma unroll
                for (int dv = 0; dv < 9; dv++)
                    acc[du * 9 + dv] += xav[t] * xbv[t + dv];
        }
        __syncthreads();
    }

#pragma unroll
    for (int q = 0; q < 81; q++) {
        float v = acc[q];
        for (int o = 16; o; o >>= 1) v += __shfl_down_sync(0xffffffffu, v, o);
        if (lane == 0) sred[wid][q] = v;
    }
    __syncthreads();
    if (tid < 81) {
        float v = 0.f;
#pragma unroll
        for (int w = 0; w < 8; w++) v += sred[w][tid];
        int u = tid / 9, vv = tid - u * 9;
        g_R[n][a][b][u][vv] = v;
        g_R[n][b][a][8 - u][8 - vv] = v;
    }
}

// ===========================================================================
// Kernel 2: P[n,(b,u,v),o] = sum_ij y[n,o,i,j]*x[n,b,i+u-2,j+v-2]  + an*d^T
// ===========================================================================
__global__ __launch_bounds__(256) void scorr_kernel(const float* __restrict__ x,
                                                    const float* __restrict__ y,
                                                    const float* __restrict__ d,
                                                    const float* __restrict__ alpha,
                                                    const float* __restrict__ regp)
{
    int n  = blockIdx.y;
    int b  = blockIdx.x & 31;
    int o0 = (blockIdx.x >> 5) * 4;

    const float* __restrict__ xb = x + ((size_t)n * CI + b) * (HH * WW);
    const float* __restrict__ yb = y + ((size_t)n * CO + o0) * (HH * WW);

    __shared__ float sya[4][16][128];
    __shared__ float sxb[20][132];
    __shared__ float sred[8][100];

    int tid  = threadIdx.x;
    int ty   = tid >> 4;
    int tx   = tid & 15;
    int lane = tid & 31;
    int wid  = tid >> 5;

    float acc[100];
#pragma unroll
    for (int q = 0; q < 100; q++) acc[q] = 0.f;

    for (int s = 0; s < 8; s++) {
        int r0 = s * 16;
#pragma unroll
        for (int o = 0; o < 4; o++) {
            const float4* src = (const float4*)(yb + (size_t)o * (HH * WW) + (size_t)(r0 + ty) * WW);
            float4* dst = (float4*)(&sya[o][ty][0]);
            dst[tx * 2]     = src[tx * 2];
            dst[tx * 2 + 1] = src[tx * 2 + 1];
        }
        for (int idx = tid; idx < 20 * 132; idx += 256) {
            int rr = idx / 132, cc = idx - rr * 132;
            int gr = r0 + rr - 2, gc = cc - 2;
            float v = 0.f;
            if (gr >= 0 && gr < HH && gc >= 0 && gc < WW)
                v = xb[(size_t)gr * WW + gc];
            sxb[rr][cc] = v;
        }
        __syncthreads();

#pragma unroll
        for (int o = 0; o < 4; o++) {
            float yav[8];
#pragma unroll
            for (int t = 0; t < 8; t++) yav[t] = sya[o][ty][tx * 8 + t];
#pragma unroll
            for (int du = 0; du < 5; du++) {
                float xbv[12];
                const float4* row = (const float4*)(&sxb[ty + du][tx * 8]);
#pragma unroll
                for (int q4 = 0; q4 < 3; q4++) {
                    float4 v = row[q4];
                    xbv[q4 * 4 + 0] = v.x; xbv[q4 * 4 + 1] = v.y;
                    xbv[q4 * 4 + 2] = v.z; xbv[q4 * 4 + 3] = v.w;
                }
#pragma unroll
                for (int t = 0; t < 8; t++)
#pragma unroll
                    for (int dv = 0; dv < 5; dv++)
                        acc[o * 25 + du * 5 + dv] += yav[t] * xbv[t + dv];
            }
        }
        __syncthreads();
    }

#pragma unroll
    for (int q = 0; q < 100; q++) {
        float v = acc[q];
        for (int oo = 16; oo; oo >>= 1) v += __shfl_down_sync(0xffffffffu, v, oo);
        if (lane == 0) sred[wid][q] = v;
    }
    __syncthreads();
    if (tid < 100) {
        float v = 0.f;
#pragma unroll
        for (int w = 0; w < 8; w++) v += sred[w][tid];
        int o = tid / 25, q = tid - o * 25;
        int k = b * 25 + q;
        float an = alpha[n] * ((float)(HH * WW) * regp[0] / (float)(DS * DS * CI));
        g_P[n][k][o0 + o] = v + an * d[((size_t)n * CO + o0 + o) * KK + k];
    }
}

// ===========================================================================
// Kernel 3: expand LOWER triangle of Q from R, add ridge on diagonal
// ===========================================================================
__global__ void assembleQ_kernel(const float* __restrict__ alpha,
                                 const float* __restrict__ regp)
{
    int n  = blockIdx.y;
    int k1 = blockIdx.x;
    int a = k1 / 25, r = (k1 / 5) % 5, s = k1 % 5;
    float an = alpha[n] * ((float)(HH * WW) * regp[0] / (float)(DS * DS * CI));
    for (int k2 = threadIdx.x; k2 <= k1; k2 += 256) {
        int bb = k2 / 25, pp = (k2 / 5) % 5, tt = k2 % 5;
        float v = g_R[n][a][bb][pp - r + 4][tt - s + 4];
        if (k2 == k1) v += an;
        g_Q[n][k1][k2] = v;
    }
}

// ===========================================================================
// potrf v4: sub-blocked factor with register diag + 20x20 diag inverses,
// then Linv(100x100) via 4 block-GEMM sweeps. dyn smem: A + V (80800 B).
// ===========================================================================
__global__ __launch_bounds__(256) void potrf_kernel(int k0, int s)
{
    int n = blockIdx.x;
    extern __shared__ float sh[];
    float (*A)[BS + 1] = (float(*)[BS + 1])sh;
    float (*V)[BS + 1] = (float(*)[BS + 1])(sh + BS * (BS + 1));
    __shared__ float dinv[BS];
    __shared__ float colb[32];
    __shared__ float Dv[5][SB][SB];
    __shared__ float Bt[4][SB][SB];

    int tid  = threadIdx.x;
    int lane = tid & 31;
    int wid  = tid >> 5;

    for (int idx = tid; idx < BS * BS; idx += 256) {
        int i = idx / BS, j = idx - i * BS;
        A[i][j] = g_Q[n][k0 + i][k0 + j];
    }
    __syncthreads();

    for (int p = 0; p < BS / SB; p++) {
        int c0 = p * SB;

        // (a) diag 20x20 factor: warp 0, lane-per-row in registers
        if (wid == 0) {
            float r[SB];
            if (lane < SB) {
#pragma unroll
                for (int j = 0; j < SB; j++) r[j] = A[c0 + lane][c0 + j];
            }
#pragma unroll
            for (int j = 0; j < SB; j++) {
                float ajj = __shfl_sync(0xffffffffu, r[j], j);
                float dd = rsqrtf(ajj);
                if (lane == j) dinv[c0 + j] = dd;
                if (lane >= j && lane < SB) r[j] *= dd;
                colb[lane] = r[j];
                __syncwarp();
#pragma unroll
                for (int k = j + 1; k < SB; k++)
                    if (lane >= k) r[k] -= r[j] * colb[k];
                __syncwarp();
            }
            if (lane < SB) {
#pragma unroll
                for (int j = 0; j < SB; j++)
                    if (j <= lane) A[c0 + lane][c0 + j] = r[j];
            }
        }
        __syncthreads();

        // (a2) invert diag block: thread c = column, forward substitution
        if (tid < SB) {
            int c = tid;
            float w[SB];
#pragma unroll
            for (int r2 = 0; r2 < SB; r2++) {
                float t = (r2 == c) ? 1.f : 0.f;
#pragma unroll
                for (int m = 0; m < SB; m++)
                    if (m < r2) t -= A[c0 + r2][c0 + m] * w[m];
                w[r2] = t * dinv[c0 + r2];
            }
#pragma unroll
            for (int r2 = 0; r2 < SB; r2++) Dv[p][r2][c] = w[r2];
        }

        // (b) panel trsm rows c0+SB..BS-1, thread-per-row
        {
            int rr = c0 + SB + tid;
            if (rr < BS) {
                float v[SB];
#pragma unroll
                for (int j = 0; j < SB; j++) v[j] = A[rr][c0 + j];
#pragma unroll
                for (int j = 0; j < SB; j++) {
                    float t = v[j];
#pragma unroll
                    for (int m = 0; m < SB; m++)
                        if (m < j) t -= A[c0 + j][c0 + m] * v[m];
                    v[j] = t * dinv[c0 + j];
                }
#pragma unroll
                for (int j = 0; j < SB; j++) A[rr][c0 + j] = v[j];
            }
        }
        __syncthreads();

        // (c) rank-20 trailing update
        int m = BS - c0 - SB;
        if (m > 0) {
            int tr = tid >> 4, tc = tid & 15;
            float c[5][5];
#pragma unroll
            for (int i = 0; i < 5; i++)
#pragma unroll
                for (int j = 0; j < 5; j++) c[i][j] = 0.f;
#pragma unroll
            for (int k = 0; k < SB; k++) {
                float ra[5], rb[5];
#pragma unroll
                for (int ii = 0; ii < 5; ii++) {
                    int row = c0 + SB + tr + ii * 16;
                    ra[ii] = (row < BS) ? A[row][c0 + k] : 0.f;
                }
#pragma unroll
                for (int jj = 0; jj < 5; jj++) {
                    int col = c0 + SB + tc + jj * 16;
                    rb[jj] = (col < BS) ? A[col][c0 + k] : 0.f;
                }
#pragma unroll
                for (int ii = 0; ii < 5; ii++)
#pragma unroll
                    for (int jj = 0; jj < 5; jj++)
                        c[ii][jj] += ra[ii] * rb[jj];
            }
#pragma unroll
            for (int ii = 0; ii < 5; ii++) {
                int row = c0 + SB + tr + ii * 16;
                if (row < BS) {
#pragma unroll
                    for (int jj = 0; jj < 5; jj++) {
                        int col = c0 + SB + tc + jj * 16;
                        if (col < BS) A[row][col] -= c[ii][jj];
                    }
                }
            }
        }
        __syncthreads();
    }

    // ------- build V = Linv via block sweeps: V[p][q] = -Dv_p*(sum L[p][m]V[m][q]) -------
    for (int idx = tid; idx < 5 * SB * SB; idx += 256) {
        int q = idx / (SB * SB), r2 = (idx / SB) % SB, cc = idx % SB;
        V[q * SB + r2][q * SB + cc] = Dv[q][r2][cc];
    }
    __syncthreads();
    for (int p = 1; p < BS / SB; p++) {
        for (int idx = tid; idx < p * SB * SB; idx += 256) {
            int q = idx / (SB * SB), r2 = (idx / SB) % SB, cc = idx % SB;
            float t = 0.f;
            for (int mm = q; mm < p; mm++) {
#pragma unroll
                for (int k = 0; k < SB; k++)
                    t += A[p * SB + r2][mm * SB + k] * V[mm * SB + k][q * SB + cc];
            }
            Bt[q][r2][cc] = t;
        }
        __syncthreads();
        for (int idx = tid; idx < p * SB * SB; idx += 256) {
            int q = idx / (SB * SB), r2 = (idx / SB) % SB, cc = idx % SB;
            float t = 0.f;
#pragma unroll
            for (int k = 0; k < SB; k++)
                t += Dv[p][r2][k] * Bt[q][k][cc];
            V[p * SB + r2][q * SB + cc] = -t;
        }
        __syncthreads();
    }

    // ------- writeback -------
    for (int idx = tid; idx < BS * BS; idx += 256) {
        int i = idx / BS, j = idx - i * BS;
        if (j <= i) g_Q[n][k0 + i][k0 + j] = A[i][j];
        g_Linv[s][n][i][j] = (j <= i) ? V[i][j] : 0.f;
    }
}

// ===========================================================================
// trsm as GEMM against Linv:
//   blocks p<rowTiles:  A21(64 rows) <- A21 * Linv^T
//   block  p==rowTiles: Z1 <- Linv * P1
// ===========================================================================
__global__ __launch_bounds__(256) void trsm_gemm(int k0, int s)
{
    int n = blockIdx.y;
    int p = blockIdx.x;
    int rows = KK - k0 - BS;
    int rowTiles = (rows + 63) >> 6;

    extern __shared__ float sh[];
    float (*Li)[BS + 1] = (float(*)[BS + 1])sh;

    int tid = threadIdx.x;
    int tr = tid >> 4, tc = tid & 15;

    for (int idx = tid; idx < BS * BS; idx += 256) {
        int i = idx / BS, j = idx - i * BS;
        Li[i][j] = g_Linv[s][n][i][j];
    }

    if (p < rowTiles) {
        float (*Ta)[BS + 1] = (float(*)[BS + 1])(sh + BS * (BS + 1));
        int rbase = k0 + BS + p * 64;
        for (int idx = tid; idx < 64 * BS; idx += 256) {
            int rr = idx / BS, k = idx - rr * BS;
            Ta[rr][k] = (rbase + rr < KK) ? g_Q[n][rbase + rr][k0 + k] : 0.f;
        }
        __syncthreads();

        float c[4][7];
#pragma unroll
        for (int i = 0; i < 4; i++)
#pragma unroll
            for (int j = 0; j < 7; j++) c[i][j] = 0.f;
#pragma unroll 4
        for (int k = 0; k < BS; k++) {
            float ra[4], rb[7];
#pragma unroll
            for (int ii = 0; ii < 4; ii++) ra[ii] = Ta[tr + 16 * ii][k];
#pragma unroll
            for (int jj = 0; jj < 7; jj++) {
                int j = tc + 16 * jj;
                rb[jj] = (j < BS) ? Li[j][k] : 0.f;
            }
#pragma unroll
            for (int ii = 0; ii < 4; ii++)
#pragma unroll
                for (int jj = 0; jj < 7; jj++)
                    c[ii][jj] += ra[ii] * rb[jj];
        }
#pragma unroll
        for (int ii = 0; ii < 4; ii++) {
            int gr = rbase + tr + 16 * ii;
            if (gr < KK) {
#pragma unroll
                for (int jj = 0; jj < 7; jj++) {
                    int j = tc + 16 * jj;
                    if (j < BS) g_Q[n][gr][k0 + j] = c[ii][jj];
                }
            }
        }
    } else {
        float (*Tp)[CO + 1] = (float(*)[CO + 1])(sh + BS * (BS + 1));
        for (int idx = tid; idx < BS * CO; idx += 256) {
            int k = idx >> 6, cc = idx & 63;
            Tp[k][cc] = g_P[n][k0 + k][cc];
        }
        __syncthreads();

        float c[7][4];
#pragma unroll
        for (int i = 0; i < 7; i++)
#pragma unroll
            for (int j = 0; j < 4; j++) c[i][j] = 0.f;
#pragma unroll 4
        for (int k = 0; k < BS; k++) {
            float ra[7], rb[4];
#pragma unroll
            for (int ii = 0; ii < 7; ii++) {
                int i = tr + 16 * ii;
                ra[ii] = (i < BS) ? Li[i][k] : 0.f;
            }
#pragma unroll
            for (int jj = 0; jj < 4; jj++) rb[jj] = Tp[k][tc + 16 * jj];
#pragma unroll
            for (int ii = 0; ii < 7; ii++)
#pragma unroll
                for (int jj = 0; jj < 4; jj++)
                    c[ii][jj] += ra[ii] * rb[jj];
        }
#pragma unroll
        for (int ii = 0; ii < 7; ii++) {
            int i = tr + 16 * ii;
            if (i < BS) {
#pragma unroll
                for (int jj = 0; jj < 4; jj++)
                    g_P[n][k0 + i][tc + 16 * jj] = c[ii][jj];
            }
        }
    }
}

// ===========================================================================
// syrk (merged): A22 -= L21*L21^T (lower tiles)  AND  P2 -= L21*Z1 (P tiles)
// ===========================================================================
__global__ __launch_bounds__(256) void syrk_kernel(int k0)
{
    int off = k0 + BS;
    int m = KK - off;
    int nt = (m + 63) >> 6;
    int ntri = nt * (nt + 1) / 2;
    int n = blockIdx.y;
    int p = blockIdx.x;

    __shared__ float LA[64][21];
    __shared__ float LB[64][21];
    int tid = threadIdx.x;
    int txx = tid & 15, tyy = tid >> 4;

    int ti, tj;
    bool pmode = (p >= ntri);
    if (pmode) { ti = p - ntri; tj = -1; }
    else {
        tj = 0;
        while (p >= nt - tj) { p -= nt - tj; tj++; }
        ti = tj + p;
    }

    float c[4][4];
#pragma unroll
    for (int i = 0; i < 4; i++)
#pragma unroll
        for (int j = 0; j < 4; j++) c[i][j] = 0.f;

    int rbase = off + ti * 64;
    int cbase = pmode ? 0 : off + tj * 64;

    for (int kk = 0; kk < BS; kk += 20) {
        for (int idx = tid; idx < 64 * 20; idx += 256) {
            int rr = idx / 20, k = idx - rr * 20;
            LA[rr][k] = (rbase + rr < KK) ? g_Q[n][rbase + rr][k0 + kk + k] : 0.f;
        }
        if (pmode) {
            for (int idx = tid; idx < 20 * 64; idx += 256) {
                int k = idx >> 6, cc = idx & 63;
                LB[cc][k] = g_P[n][k0 + kk + k][cc];
            }
        } else {
            for (int idx = tid; idx < 64 * 20; idx += 256) {
                int rr = idx / 20, k = idx - rr * 20;
                LB[rr][k] = (cbase + rr < KK) ? g_Q[n][cbase + rr][k0 + kk + k] : 0.f;
            }
        }
        __syncthreads();
#pragma unroll
        for (int k = 0; k < 20; k++) {
            float ra[4], rb[4];
#pragma unroll
            for (int i = 0; i < 4; i++) ra[i] = LA[tyy * 4 + i][k];
#pragma unroll
            for (int j = 0; j < 4; j++) rb[j] = LB[txx * 4 + j][k];
#pragma unroll
            for (int i = 0; i < 4; i++)
#pragma unroll
                for (int j = 0; j < 4; j++) c[i][j] += ra[i] * rb[j];
        }
        __syncthreads();
    }
#pragma unroll
    for (int i = 0; i < 4; i++) {
        int gr = rbase + tyy * 4 + i;
        if (gr < KK) {
            if (pmode) {
#pragma unroll
                for (int j = 0; j < 4; j++)
                    g_P[n][gr][txx * 4 + j] -= c[i][j];
            } else {
#pragma unroll
                for (int j = 0; j < 4; j++) {
                    int gc = cbase + txx * 4 + j;
                    if (gc < KK) g_Q[n][gr][gc] -= c[i][j];
                }
            }
        }
    }
}

// ===========================================================================
// backward diag solve as GEMM: Z_panel <- Linv^T * Z_panel
// ===========================================================================
__global__ __launch_bounds__(256) void bwd_gemm(int k0, int s)
{
    int n = blockIdx.y;
    int half = blockIdx.x;

    extern __shared__ float sh[];
    float (*Li)[BS + 1] = (float(*)[BS + 1])sh;
    float (*Zp)[33]     = (float(*)[33])(sh + BS * (BS + 1));

    int tid = threadIdx.x;
    int tr = tid >> 4, tc = tid & 15;

    for (int idx = tid; idx < BS * BS; idx += 256) {
        int i = idx / BS, j = idx - i * BS;
        Li[i][j] = g_Linv[s][n][i][j];
    }
    for (int idx = tid; idx < BS * 32; idx += 256) {
        int k = idx >> 5, cc = idx & 31;
        Zp[k][cc] = g_P[n][k0 + k][half * 32 + cc];
    }
    __syncthreads();

    float c[7][2];
#pragma unroll
    for (int i = 0; i < 7; i++)
#pragma unroll
        for (int j = 0; j < 2; j++) c[i][j] = 0.f;
#pragma unroll 4
    for (int k = 0; k < BS; k++) {
        float ra[7], rb[2];
#pragma unroll
        for (int ii = 0; ii < 7; ii++) {
            int i = tr + 16 * ii;
            ra[ii] = (i < BS) ? Li[k][i] : 0.f;
        }
#pragma unroll
        for (int jj = 0; jj < 2; jj++) rb[jj] = Zp[k][tc + 16 * jj];
#pragma unroll
        for (int ii = 0; ii < 7; ii++)
#pragma unroll
            for (int jj = 0; jj < 2; jj++)
                c[ii][jj] += ra[ii] * rb[jj];
    }
#pragma unroll
    for (int ii = 0; ii < 7; ii++) {
        int i = tr + 16 * ii;
        if (i < BS) {
#pragma unroll
            for (int jj = 0; jj < 2; jj++)
                g_P[n][k0 + i][half * 32 + tc + 16 * jj] = c[ii][jj];
        }
    }
}

// backward update: Z[0:k0, :] -= L[k0:k0+100, 0:k0]^T * D[k0:k0+100, :]
__global__ __launch_bounds__(256) void bsolve_update_kernel(int k0)
{
    int n = blockIdx.y;
    int rbase = blockIdx.x * 64;

    __shared__ float AT[20][65];
    __shared__ float BB[20][65];
    int tid = threadIdx.x;
    int txx = tid & 15, tyy = tid >> 4;

    float c[4][4];
#pragma unroll
    for (int i = 0; i < 4; i++)
#pragma unroll
        for (int j = 0; j < 4; j++) c[i][j] = 0.f;

    for (int kk = 0; kk < BS; kk += 20) {
        for (int idx = tid; idx < 20 * 64; idx += 256) {
            int k = idx >> 6, rl = idx & 63;
            AT[k][rl] = g_Q[n][k0 + kk + k][rbase + rl];
        }
        for (int idx = tid; idx < 20 * 64; idx += 256) {
            int k = idx >> 6, cc = idx & 63;
            BB[k][cc] = g_P[n][k0 + kk + k][cc];
        }
        __syncthreads();
#pragma unroll
        for (int k = 0; k < 20; k++) {
            float ra[4], rb[4];
#pragma unroll
            for (int i = 0; i < 4; i++) ra[i] = AT[k][tyy * 4 + i];
#pragma unroll
            for (int j = 0; j < 4; j++) rb[j] = BB[k][txx * 4 + j];
#pragma unroll
            for (int i = 0; i < 4; i++)
#pragma unroll
                for (int j = 0; j < 4; j++) c[i][j] += ra[i] * rb[j];
        }
        __syncthreads();
    }
#pragma unroll
    for (int i = 0; i < 4; i++) {
        int gr = rbase + tyy * 4 + i;
        if (gr < k0) {
#pragma unroll
            for (int j = 0; j < 4; j++)
                g_P[n][gr][txx * 4 + j] -= c[i][j];
        }
    }
}

// final transpose: out[n][o][k] = P[n][k][o]
__global__ __launch_bounds__(256) void output_kernel(float* __restrict__ out)
{
    __shared__ float t[32][33];
    int n  = blockIdx.z;
    int kb = blockIdx.x * 32;
    int ob = blockIdx.y * 32;
    int tx = threadIdx.x & 31, ty4 = threadIdx.x >> 5;

    for (int i = ty4; i < 32; i += 8)
        t[i][tx] = g_P[n][kb + i][ob + tx];
    __syncthreads();
    for (int i = ty4; i < 32; i += 8)
        out[((size_t)n * CO + ob + i) * KK + kb + tx] = t[tx][i];
}

// ===========================================================================
extern "C" void kernel_launch(void* const* d_in, const int* in_sizes, int n_in,
                              void* d_out, int out_size)
{
    const float* x     = (const float*)d_in[0];
    const float* d     = (const float*)d_in[1];
    const float* y     = (const float*)d_in[2];
    const float* alpha = (const float*)d_in[3];
    const float* regp  = (const float*)d_in[4];

    static int attr_done = 0;
    if (!attr_done) {
        cudaFuncSetAttribute(potrf_kernel, cudaFuncAttributeMaxDynamicSharedMemorySize, 2 * BS * (BS + 1) * 4);
        cudaFuncSetAttribute(trsm_gemm,    cudaFuncAttributeMaxDynamicSharedMemorySize, (BS * (BS + 1) + BS * (CO + 1)) * 4);
        cudaFuncSetAttribute(bwd_gemm,     cudaFuncAttributeMaxDynamicSharedMemorySize, (BS * (BS + 1) + BS * 33) * 4);
        attr_done = 1;
    }

    gram_kernel <<<dim3(528, NBATCH), 256>>>(x);
    scorr_kernel<<<dim3(512, NBATCH), 256>>>(x, y, d, alpha, regp);
    assembleQ_kernel<<<dim3(KK, NBATCH), 256>>>(alpha, regp);

    // blocked Cholesky with fused forward solve
    for (int s = 0; s < NSTEP; s++) {
        int k0 = s * BS;
        potrf_kernel<<<NBATCH, 256, 2 * BS * (BS + 1) * 4>>>(k0, s);
        int rows = KK - k0 - BS;
        int rowTiles = (rows + 63) / 64;
        trsm_gemm<<<dim3(rowTiles + 1, NBATCH), 256, (BS * (BS + 1) + BS * (CO + 1)) * 4>>>(k0, s);
        if (rows > 0) {
            int nt = (rows + 63) / 64;
            int tiles = nt * (nt + 1) / 2 + nt;
            syrk_kernel<<<dim3(tiles, NBATCH), 256>>>(k0);
        }
    }
    // backward substitution
    for (int s = NSTEP - 1; s >= 0; s--) {
        int k0 = s * BS;
        bwd_gemm<<<dim3(2, NBATCH), 256, (BS * (BS + 1) + BS * 33) * 4>>>(k0, s);
        if (k0 > 0)
            bsolve_update_kernel<<<dim3((k0 + 63) / 64, NBATCH), 256>>>(k0);
    }

    output_kernel<<<dim3(KK / 32, CO / 32, NBATCH), 256>>>((float*)d_out);
}